// round 1
// baseline (speedup 1.0000x reference)
#include <cuda_runtime.h>
#include <math.h>

#define BB 2
#define NN 2048
#define DD 1024
#define HH 8
#define QH_ 16
#define DH_ 64

// ---------------- scratch (device globals; no allocations allowed) ----------
__device__ float g_xn[BB*NN*DD];           // rmsnorm(x)                 [4096,1024]
__device__ float g_q [BB*NN*QH_*DH_];      // x@Wq                       [4096,1024]
__device__ float g_kv[BB*NN*2*HH*DH_];     // x@Wkv                      [4096,1024]
__device__ float g_qn[BB*QH_*NN*DH_];      // normalized q  [b][qh][n][d]
__device__ float g_kn[BB*HH*NN*DH_];       // normalized k  [b][h][n][d]
__device__ float g_vt[BB*HH*NN*DH_];       // v transposed  [b][h][n][d]
__device__ float g_oq[BB*QH_*NN*DH_];      // per-query-head attn out
__device__ float g_ao[BB*NN*HH*DH_];       // group-summed  [bn][h*64+d]

// ---------------- rmsnorm ---------------------------------------------------
__global__ void rmsnorm_kernel(const float* __restrict__ x,
                               const float* __restrict__ w) {
    int row = blockIdx.x;
    const float* xr = x + (size_t)row * DD;
    float ss = 0.f;
    for (int i = threadIdx.x; i < DD; i += 256) { float v = xr[i]; ss = fmaf(v, v, ss); }
    __shared__ float red[8];
    #pragma unroll
    for (int o = 16; o; o >>= 1) ss += __shfl_xor_sync(~0u, ss, o);
    if ((threadIdx.x & 31) == 0) red[threadIdx.x >> 5] = ss;
    __syncthreads();
    if (threadIdx.x < 8) {
        ss = red[threadIdx.x];
        #pragma unroll
        for (int o = 4; o; o >>= 1) ss += __shfl_xor_sync(0xff, ss, o);
        if (threadIdx.x == 0) red[0] = ss;
    }
    __syncthreads();
    float r = rsqrtf(red[0] * (1.0f / DD) + 1.1920929e-07f);
    float* yr = g_xn + (size_t)row * DD;
    for (int i = threadIdx.x; i < DD; i += 256) yr[i] = xr[i] * r * w[i];
}

// ---------------- generic fp32 SGEMM: C[M,N] = A[M,K] @ B[K,N] ---------------
__global__ void __launch_bounds__(256)
gemm_kernel(const float* __restrict__ A, const float* __restrict__ B,
            float* __restrict__ C, int M, int Nc, int K) {
    __shared__ float As[8][128];
    __shared__ float Bs[8][128];
    int bx = blockIdx.x, by = blockIdx.y;
    int tid = threadIdx.x;
    int tx = tid & 15, ty = tid >> 4;
    const float* Ab = A + (size_t)by * 128 * K;
    const float* Bb = B + (size_t)bx * 128;
    float acc[8][8];
    #pragma unroll
    for (int i = 0; i < 8; i++)
        #pragma unroll
        for (int j = 0; j < 8; j++) acc[i][j] = 0.f;

    for (int k0 = 0; k0 < K; k0 += 8) {
        #pragma unroll
        for (int i = 0; i < 4; i++) {
            int idx = tid + i * 256; int m = idx >> 3, k = idx & 7;
            As[k][m] = Ab[(size_t)m * K + k0 + k];
        }
        #pragma unroll
        for (int i = 0; i < 4; i++) {
            int idx = tid + i * 256; int k = idx >> 7, n = idx & 127;
            Bs[k][n] = Bb[(size_t)(k0 + k) * Nc + n];
        }
        __syncthreads();
        #pragma unroll
        for (int k = 0; k < 8; k++) {
            float4 a0 = *(const float4*)&As[k][ty * 8];
            float4 a1 = *(const float4*)&As[k][ty * 8 + 4];
            float4 b0 = *(const float4*)&Bs[k][tx * 8];
            float4 b1 = *(const float4*)&Bs[k][tx * 8 + 4];
            float ar[8] = {a0.x, a0.y, a0.z, a0.w, a1.x, a1.y, a1.z, a1.w};
            float br[8] = {b0.x, b0.y, b0.z, b0.w, b1.x, b1.y, b1.z, b1.w};
            #pragma unroll
            for (int i = 0; i < 8; i++)
                #pragma unroll
                for (int j = 0; j < 8; j++)
                    acc[i][j] = fmaf(ar[i], br[j], acc[i][j]);
        }
        __syncthreads();
    }
    float* Cb = C + ((size_t)(by * 128 + ty * 8)) * Nc + bx * 128 + tx * 8;
    #pragma unroll
    for (int i = 0; i < 8; i++) {
        float4 c0 = make_float4(acc[i][0], acc[i][1], acc[i][2], acc[i][3]);
        float4 c1 = make_float4(acc[i][4], acc[i][5], acc[i][6], acc[i][7]);
        *(float4*)&Cb[(size_t)i * Nc]     = c0;
        *(float4*)&Cb[(size_t)i * Nc + 4] = c1;
    }
}

// ---------------- per-head l2norm * (gamma+1)*sqrt(dh), q path --------------
__global__ void qnorm_kernel(const float* __restrict__ gamma) {
    int gw = (blockIdx.x * 256 + threadIdx.x) >> 5;
    int lane = threadIdx.x & 31;
    if (gw >= BB * NN * QH_) return;
    int qh = gw % QH_; int bn = gw / QH_;
    int n = bn % NN, b = bn / NN;
    const float* src = g_q + ((size_t)bn * QH_ + qh) * DH_;
    float v0 = src[lane], v1 = src[lane + 32];
    float ss = v0 * v0 + v1 * v1;
    #pragma unroll
    for (int o = 16; o; o >>= 1) ss += __shfl_xor_sync(~0u, ss, o);
    float inv = 1.0f / fmaxf(sqrtf(ss), 1e-12f);
    float g0 = (gamma[qh * DH_ + lane] + 1.f) * 8.f;
    float g1 = (gamma[qh * DH_ + lane + 32] + 1.f) * 8.f;
    float* dst = g_qn + (((size_t)(b * QH_ + qh)) * NN + n) * DH_;
    dst[lane]      = v0 * inv * g0;
    dst[lane + 32] = v1 * inv * g1;
}

// ---------------- k norm + v transpose --------------------------------------
__global__ void kvnorm_kernel(const float* __restrict__ gamma) {
    int gw = (blockIdx.x * 256 + threadIdx.x) >> 5;
    int lane = threadIdx.x & 31;
    if (gw >= BB * NN * HH) return;
    int h = gw % HH; int bn = gw / HH;
    int n = bn % NN, b = bn / NN;
    const float* ksrc = g_kv + (size_t)bn * (2 * HH * DH_) + h * DH_;
    const float* vsrc = ksrc + HH * DH_;
    float v0 = ksrc[lane], v1 = ksrc[lane + 32];
    float ss = v0 * v0 + v1 * v1;
    #pragma unroll
    for (int o = 16; o; o >>= 1) ss += __shfl_xor_sync(~0u, ss, o);
    float inv = 1.0f / fmaxf(sqrtf(ss), 1e-12f);
    float g0 = (gamma[h * DH_ + lane] + 1.f) * 8.f;
    float g1 = (gamma[h * DH_ + lane + 32] + 1.f) * 8.f;
    size_t base = (((size_t)(b * HH + h)) * NN + n) * DH_;
    g_kn[base + lane]      = v0 * inv * g0;
    g_kn[base + lane + 32] = v1 * inv * g1;
    g_vt[base + lane]      = vsrc[lane];
    g_vt[base + lane + 32] = vsrc[lane + 32];
}

// ---------------- flash attention with tanh softcap, causal -----------------
// grid: (N/64, QH, B), 256 threads, dynamic smem 49408 B
__global__ void __launch_bounds__(256) attn_kernel() {
    extern __shared__ float sm[];
    float* Qs = sm;                    // [64][64]
    float* Kt = sm + 4096;             // [64][65]  K^T, later reused as P[64][65]
    float* Vs = sm + 4096 + 64 * 65;   // [64][64]
    const int qt = blockIdx.x, qh = blockIdx.y, b = blockIdx.z;
    const int h = qh >> 1;
    const int tid = threadIdx.x, warp = tid >> 5, lane = tid & 31;
    const float* qbase = g_qn + (((size_t)(b * QH_ + qh)) * NN + qt * 64) * DH_;
    const float* kbase = g_kn + ((size_t)(b * HH + h)) * NN * DH_;
    const float* vbase = g_vt + ((size_t)(b * HH + h)) * NN * DH_;

    for (int i = tid; i < 4096; i += 256) Qs[i] = qbase[i];

    float m[8], l[8], a0[8], a1[8];
    #pragma unroll
    for (int r = 0; r < 8; r++) { m[r] = -3.0e38f; l[r] = 0.f; a0[r] = 0.f; a1[r] = 0.f; }
    const int rb = warp * 8;

    for (int jt = 0; jt <= qt; jt++) {
        __syncthreads();
        const float* kt = kbase + (size_t)jt * 64 * DH_;
        const float* vv = vbase + (size_t)jt * 64 * DH_;
        for (int i = tid; i < 4096; i += 256) {
            int j = i >> 6, d = i & 63;
            Kt[d * 65 + j] = kt[i];
            Vs[i] = vv[i];
        }
        __syncthreads();

        float s0[8], s1[8];
        #pragma unroll
        for (int r = 0; r < 8; r++) { s0[r] = 0.f; s1[r] = 0.f; }
        #pragma unroll 4
        for (int d = 0; d < 64; d++) {
            float k0 = Kt[d * 65 + lane], k1 = Kt[d * 65 + lane + 32];
            #pragma unroll
            for (int r = 0; r < 8; r++) {
                float qv = Qs[(rb + r) * 64 + d];
                s0[r] = fmaf(qv, k0, s0[r]);
                s1[r] = fmaf(qv, k1, s1[r]);
            }
        }
        __syncthreads();   // everyone finished reading Kt before we overwrite with P

        int ig0 = qt * 64 + rb;
        int jg0 = jt * 64;
        #pragma unroll
        for (int r = 0; r < 8; r++) {
            int ig = ig0 + r;
            // softcap BEFORE scale (faithful): tanh(s/50)*50 * (1/8)
            float x0 = tanhf(s0[r] * 0.02f) * 6.25f;
            float x1 = tanhf(s1[r] * 0.02f) * 6.25f;
            if (jg0 + lane      > ig) x0 = -3.0e38f;
            if (jg0 + lane + 32 > ig) x1 = -3.0e38f;
            float mx = fmaxf(x0, x1);
            #pragma unroll
            for (int o = 16; o; o >>= 1) mx = fmaxf(mx, __shfl_xor_sync(~0u, mx, o));
            float mn = fmaxf(m[r], mx);
            float alpha = __expf(m[r] - mn);
            float p0 = __expf(x0 - mn), p1 = __expf(x1 - mn);
            float ps = p0 + p1;
            #pragma unroll
            for (int o = 16; o; o >>= 1) ps += __shfl_xor_sync(~0u, ps, o);
            l[r] = l[r] * alpha + ps;
            m[r] = mn;
            a0[r] *= alpha; a1[r] *= alpha;
            Kt[(rb + r) * 65 + lane]      = p0;
            Kt[(rb + r) * 65 + lane + 32] = p1;
        }
        __syncwarp();

        #pragma unroll 4
        for (int jj = 0; jj < 64; jj++) {
            float v0 = Vs[jj * 64 + lane], v1 = Vs[jj * 64 + lane + 32];
            #pragma unroll
            for (int r = 0; r < 8; r++) {
                float p = Kt[(rb + r) * 65 + jj];
                a0[r] = fmaf(p, v0, a0[r]);
                a1[r] = fmaf(p, v1, a1[r]);
            }
        }
    }

    float* ob = g_oq + (((size_t)(b * QH_ + qh)) * NN + qt * 64 + rb) * DH_;
    #pragma unroll
    for (int r = 0; r < 8; r++) {
        float inv = 1.0f / l[r];
        ob[r * 64 + lane]      = a0[r] * inv;
        ob[r * 64 + lane + 32] = a1[r] * inv;
    }
}

// ---------------- sum over group axis g (2 query heads per kv head) ---------
__global__ void combine_kernel() {
    int i = blockIdx.x * 256 + threadIdx.x;   // over BB*NN*HH*DH_
    if (i >= BB * NN * HH * DH_) return;
    int d = i & 63;
    int h = (i >> 6) & 7;
    int bn = i >> 9;
    int n = bn & (NN - 1);
    int b = bn >> 11;
    size_t o0 = (((size_t)(b * QH_ + 2 * h)) * NN + n) * DH_ + d;
    size_t o1 = o0 + (size_t)NN * DH_;
    g_ao[i] = g_oq[o0] + g_oq[o1];
}

// ---------------- launch -----------------------------------------------------
extern "C" void kernel_launch(void* const* d_in, const int* in_sizes, int n_in,
                              void* d_out, int out_size) {
    const float* tokens  = (const float*)d_in[0];
    const float* norm_w  = (const float*)d_in[1];
    const float* Wq      = (const float*)d_in[2];
    const float* Wkv     = (const float*)d_in[3];
    const float* Wout    = (const float*)d_in[4];
    const float* q_gamma = (const float*)d_in[5];
    const float* k_gamma = (const float*)d_in[6];
    float* out = (float*)d_out;

    float *xn, *q, *kv, *ao;
    cudaGetSymbolAddress((void**)&xn, g_xn);
    cudaGetSymbolAddress((void**)&q,  g_q);
    cudaGetSymbolAddress((void**)&kv, g_kv);
    cudaGetSymbolAddress((void**)&ao, g_ao);

    // 1. rmsnorm
    rmsnorm_kernel<<<BB * NN, 256>>>(tokens, norm_w);

    // 2. projections
    dim3 pgrid(1024 / 128, (BB * NN) / 128);
    gemm_kernel<<<pgrid, 256>>>(xn, Wq,  q,  BB * NN, 1024, 1024);
    gemm_kernel<<<pgrid, 256>>>(xn, Wkv, kv, BB * NN, 1024, 1024);

    // 3. per-head norms + v transpose
    qnorm_kernel<<<(BB * NN * QH_ * 32) / 256, 256>>>(q_gamma);
    kvnorm_kernel<<<(BB * NN * HH * 32) / 256, 256>>>(k_gamma);

    // 4. attention
    int smem = (4096 + 64 * 65 + 4096) * sizeof(float);  // 49408
    cudaFuncSetAttribute(attn_kernel, cudaFuncAttributeMaxDynamicSharedMemorySize, smem);
    dim3 agrid(NN / 64, QH_, BB);
    attn_kernel<<<agrid, 256, smem>>>();

    // 5. group sum + output projection
    combine_kernel<<<(BB * NN * HH * DH_) / 256, 256>>>();
    dim3 ogrid(1024 / 128, (BB * NN) / 128);
    gemm_kernel<<<ogrid, 256>>>(ao, Wout, out, BB * NN, 1024, HH * DH_);
}

// round 3
// speedup vs baseline: 1.6148x; 1.6148x over previous
#include <cuda_runtime.h>
#include <cuda_fp16.h>
#include <cstdint>
#include <math.h>

#define BB 2
#define NN 2048
#define DD 1024
#define HH 8
#define QH_ 16
#define DH_ 64
#define MM (BB*NN)

// ---------------- scratch ----------------------------------------------------
__device__ __half g_xh [MM*DD];          // rmsnorm(x), fp16      [4096][1024]
__device__ __half g_wq [DD*DD];          // Wq^T  fp16 [n][k]     [1024][1024]
__device__ __half g_wkv[DD*DD];          // Wkv^T fp16 [n][k]     [1024][1024]
__device__ __half g_wo [DD*HH*DH_];      // Wout^T fp16 [n][k]    [1024][512]
__device__ float  g_q  [MM*QH_*DH_];
__device__ float  g_kv [MM*2*HH*DH_];
__device__ float  g_qn [BB*QH_*NN*DH_];
__device__ float  g_kn [BB*HH*NN*DH_];
__device__ float  g_vt [BB*HH*NN*DH_];
__device__ float  g_oq [BB*QH_*NN*DH_];
__device__ __half g_ah [MM*HH*DH_];      // combined attn out fp16 [4096][512]

// ---------------- mma / ldmatrix helpers -------------------------------------
__device__ __forceinline__ void ldsm4(unsigned& r0, unsigned& r1, unsigned& r2,
                                      unsigned& r3, unsigned addr) {
    asm volatile("ldmatrix.sync.aligned.m8n8.x4.shared.b16 {%0,%1,%2,%3}, [%4];"
                 : "=r"(r0), "=r"(r1), "=r"(r2), "=r"(r3) : "r"(addr));
}
__device__ __forceinline__ void mma16816(float* c, const unsigned* a,
                                         unsigned b0, unsigned b1) {
    asm volatile(
        "mma.sync.aligned.m16n8k16.row.col.f32.f16.f16.f32 "
        "{%0,%1,%2,%3},{%4,%5,%6,%7},{%8,%9},{%0,%1,%2,%3};"
        : "+f"(c[0]), "+f"(c[1]), "+f"(c[2]), "+f"(c[3])
        : "r"(a[0]), "r"(a[1]), "r"(a[2]), "r"(a[3]), "r"(b0), "r"(b1));
}

// ---------------- rmsnorm -> fp16 --------------------------------------------
__global__ void rmsnorm_kernel(const float* __restrict__ x,
                               const float* __restrict__ w) {
    int row = blockIdx.x;
    const float* xr = x + (size_t)row * DD;
    float ss = 0.f;
    for (int i = threadIdx.x; i < DD; i += 256) { float v = xr[i]; ss = fmaf(v, v, ss); }
    __shared__ float red[8];
    #pragma unroll
    for (int o = 16; o; o >>= 1) ss += __shfl_xor_sync(~0u, ss, o);
    if ((threadIdx.x & 31) == 0) red[threadIdx.x >> 5] = ss;
    __syncthreads();
    if (threadIdx.x < 8) {
        ss = red[threadIdx.x];
        #pragma unroll
        for (int o = 4; o; o >>= 1) ss += __shfl_xor_sync(0xff, ss, o);
        if (threadIdx.x == 0) red[0] = ss;
    }
    __syncthreads();
    float r = rsqrtf(red[0] * (1.0f / DD) + 1.1920929e-07f);
    __half* yr = g_xh + (size_t)row * DD;
    for (int i = threadIdx.x; i < DD; i += 256) yr[i] = __float2half(xr[i] * r * w[i]);
}

// ---------------- weight transpose+convert: W[K][N] f32 -> Wt[N][K] f16 ------
__global__ void wtrans_kernel(const float* __restrict__ W, __half* __restrict__ Wt,
                              int K, int N) {
    __shared__ float t[32][33];
    int n0 = blockIdx.x * 32, k0 = blockIdx.y * 32;
    int x = threadIdx.x, y = threadIdx.y;
    #pragma unroll
    for (int i = 0; i < 32; i += 8)
        t[y + i][x] = W[(size_t)(k0 + y + i) * N + n0 + x];
    __syncthreads();
    #pragma unroll
    for (int i = 0; i < 32; i += 8)
        Wt[(size_t)(n0 + y + i) * K + k0 + x] = __float2half(t[x][y + i]);
}

// ---------------- fp16 tensor-core GEMM: C[M][1024] = A[M][K] @ Bt[N][K]^T ---
// CTA tile 128x128, K-chunk 32, double-buffered smem, 8 warps of 32m x 64n.
#define ASTR 40          // smem row stride in halves (conflict-free ldmatrix)
#define ABUF (128*ASTR)  // one buffer: 5120 halves
__global__ void __launch_bounds__(256, 2)
hgemm_kernel(const __half* __restrict__ A, const __half* __restrict__ Bt,
             float* __restrict__ C, int K) {
    __shared__ __half sh[4 * ABUF];      // As buf0/1, Bs buf0/1 : 40 KB
    const int tid = threadIdx.x;
    const int lane = tid & 31;
    const int warp = tid >> 5;
    const int wm = (warp >> 1) << 5;     // warp m offset (0..96)
    const int wn = (warp & 1) << 6;      // warp n offset (0/64)
    const int bm = blockIdx.y << 7;
    const int bn = blockIdx.x << 7;

    const int lr = tid >> 2;             // 0..63
    const int lg = (tid & 3) << 3;       // 0,8,16,24 (halves)
    const __half* Ag = A + (size_t)(bm + lr) * K + lg;
    const __half* Bg = Bt + (size_t)(bn + lr) * K + lg;
    const size_t rowskip = (size_t)64 * K;

    unsigned sb;
    asm("{ .reg .u64 t; cvta.to.shared.u64 t, %1; cvt.u32.u64 %0, t; }"
        : "=r"(sb) : "l"(sh));
    const int aRow = wm + (lane & 15);
    const int aK   = (lane >> 4) << 3;
    const int bRow = wn + (lane & 7) + ((lane >> 4) << 3);
    const int bK   = ((lane >> 3) & 1) << 3;
    const unsigned ldA = sb + (unsigned)(aRow * ASTR + aK) * 2u;
    const unsigned ldB = sb + (unsigned)(2 * ABUF + bRow * ASTR + bK) * 2u;

    float acc[2][8][4];
    #pragma unroll
    for (int i = 0; i < 2; i++) {
        #pragma unroll
        for (int j = 0; j < 8; j++) {
            #pragma unroll
            for (int q = 0; q < 4; q++) acc[i][j][q] = 0.f;
        }
    }

    // prologue: chunk 0 -> buf 0
    uint4 pa0 = *(const uint4*)Ag;
    uint4 pa1 = *(const uint4*)(Ag + rowskip);
    uint4 pb0 = *(const uint4*)Bg;
    uint4 pb1 = *(const uint4*)(Bg + rowskip);
    {
        __half* as = sh + lr * ASTR + lg;
        __half* bs = sh + 2 * ABUF + lr * ASTR + lg;
        *(uint4*)as = pa0;
        *(uint4*)(as + 64 * ASTR) = pa1;
        *(uint4*)bs = pb0;
        *(uint4*)(bs + 64 * ASTR) = pb1;
    }
    __syncthreads();

    const int nch = K >> 5;
    for (int c = 0; c < nch; c++) {
        if (c + 1 < nch) {
            const __half* An = Ag + (c + 1) * 32;
            const __half* Bn = Bg + (c + 1) * 32;
            pa0 = *(const uint4*)An;
            pa1 = *(const uint4*)(An + rowskip);
            pb0 = *(const uint4*)Bn;
            pb1 = *(const uint4*)(Bn + rowskip);
        }
        const unsigned bo = (unsigned)(c & 1) * (unsigned)(ABUF * 2);
        #pragma unroll
        for (int ks = 0; ks < 2; ks++) {
            unsigned a0r[4], a1r[4], b[4][4];
            ldsm4(a0r[0], a0r[1], a0r[2], a0r[3], ldA + bo + ks * 32);
            ldsm4(a1r[0], a1r[1], a1r[2], a1r[3],
                  ldA + bo + 16 * ASTR * 2 + ks * 32);
            #pragma unroll
            for (int p = 0; p < 4; p++)
                ldsm4(b[p][0], b[p][1], b[p][2], b[p][3],
                      ldB + bo + (unsigned)(p * 16 * ASTR * 2) + ks * 32);
            #pragma unroll
            for (int p = 0; p < 4; p++) {
                mma16816(acc[0][2 * p],     a0r, b[p][0], b[p][1]);
                mma16816(acc[0][2 * p + 1], a0r, b[p][2], b[p][3]);
                mma16816(acc[1][2 * p],     a1r, b[p][0], b[p][1]);
                mma16816(acc[1][2 * p + 1], a1r, b[p][2], b[p][3]);
            }
        }
        if (c + 1 < nch) {
            __syncthreads();
            __half* as = sh + ((c + 1) & 1) * ABUF + lr * ASTR + lg;
            __half* bs = as + 2 * ABUF;
            *(uint4*)as = pa0;
            *(uint4*)(as + 64 * ASTR) = pa1;
            *(uint4*)bs = pb0;
            *(uint4*)(bs + 64 * ASTR) = pb1;
            __syncthreads();
        }
    }

    // epilogue
    const int er = lane >> 2;
    const int ec = (lane & 3) << 1;
    #pragma unroll
    for (int mt = 0; mt < 2; mt++) {
        #pragma unroll
        for (int nt = 0; nt < 8; nt++) {
            int r0 = bm + wm + mt * 16 + er;
            int c0 = bn + wn + nt * 8 + ec;
            *(float2*)&C[(size_t)r0 * 1024 + c0] =
                make_float2(acc[mt][nt][0], acc[mt][nt][1]);
            *(float2*)&C[(size_t)(r0 + 8) * 1024 + c0] =
                make_float2(acc[mt][nt][2], acc[mt][nt][3]);
        }
    }
}

// ---------------- per-head l2norm * (gamma+1)*sqrt(dh), q path ---------------
__global__ void qnorm_kernel(const float* __restrict__ gamma) {
    int gw = (blockIdx.x * 256 + threadIdx.x) >> 5;
    int lane = threadIdx.x & 31;
    if (gw >= BB * NN * QH_) return;
    int qh = gw % QH_;
    int bn = gw / QH_;
    int n = bn % NN, b = bn / NN;
    const float* src = g_q + ((size_t)bn * QH_ + qh) * DH_;
    float v0 = src[lane], v1 = src[lane + 32];
    float ss = v0 * v0 + v1 * v1;
    #pragma unroll
    for (int o = 16; o; o >>= 1) ss += __shfl_xor_sync(~0u, ss, o);
    float inv = 1.0f / fmaxf(sqrtf(ss), 1e-12f);
    float g0 = (gamma[qh * DH_ + lane] + 1.f) * 8.f;
    float g1 = (gamma[qh * DH_ + lane + 32] + 1.f) * 8.f;
    float* dst = g_qn + (((size_t)(b * QH_ + qh)) * NN + n) * DH_;
    dst[lane]      = v0 * inv * g0;
    dst[lane + 32] = v1 * inv * g1;
}

// ---------------- k norm + v transpose ---------------------------------------
__global__ void kvnorm_kernel(const float* __restrict__ gamma) {
    int gw = (blockIdx.x * 256 + threadIdx.x) >> 5;
    int lane = threadIdx.x & 31;
    if (gw >= BB * NN * HH) return;
    int h = gw % HH;
    int bn = gw / HH;
    int n = bn % NN, b = bn / NN;
    const float* ksrc = g_kv + (size_t)bn * (2 * HH * DH_) + h * DH_;
    const float* vsrc = ksrc + HH * DH_;
    float v0 = ksrc[lane], v1 = ksrc[lane + 32];
    float ss = v0 * v0 + v1 * v1;
    #pragma unroll
    for (int o = 16; o; o >>= 1) ss += __shfl_xor_sync(~0u, ss, o);
    float inv = 1.0f / fmaxf(sqrtf(ss), 1e-12f);
    float g0 = (gamma[h * DH_ + lane] + 1.f) * 8.f;
    float g1 = (gamma[h * DH_ + lane + 32] + 1.f) * 8.f;
    size_t base = (((size_t)(b * HH + h)) * NN + n) * DH_;
    g_kn[base + lane]      = v0 * inv * g0;
    g_kn[base + lane + 32] = v1 * inv * g1;
    g_vt[base + lane]      = vsrc[lane];
    g_vt[base + lane + 32] = vsrc[lane + 32];
}

// ---------------- flash attention (fp32 SIMT), causal + tanh softcap ---------
__global__ void __launch_bounds__(256) attn_kernel() {
    extern __shared__ float sm[];
    float* Qs = sm;
    float* Kt = sm + 4096;
    float* Vs = sm + 4096 + 64 * 65;
    const int qt = blockIdx.x, qh = blockIdx.y, b = blockIdx.z;
    const int h = qh >> 1;
    const int tid = threadIdx.x, warp = tid >> 5, lane = tid & 31;
    const float* qbase = g_qn + (((size_t)(b * QH_ + qh)) * NN + qt * 64) * DH_;
    const float* kbase = g_kn + ((size_t)(b * HH + h)) * NN * DH_;
    const float* vbase = g_vt + ((size_t)(b * HH + h)) * NN * DH_;

    for (int i = tid; i < 4096; i += 256) Qs[i] = qbase[i];

    float m[8], l[8], a0[8], a1[8];
    #pragma unroll
    for (int r = 0; r < 8; r++) { m[r] = -3.0e38f; l[r] = 0.f; a0[r] = 0.f; a1[r] = 0.f; }
    const int rb = warp * 8;

    for (int jt = 0; jt <= qt; jt++) {
        __syncthreads();
        const float* kt = kbase + (size_t)jt * 64 * DH_;
        const float* vv = vbase + (size_t)jt * 64 * DH_;
        for (int i = tid; i < 4096; i += 256) {
            int j = i >> 6, d = i & 63;
            Kt[d * 65 + j] = kt[i];
            Vs[i] = vv[i];
        }
        __syncthreads();

        float s0[8], s1[8];
        #pragma unroll
        for (int r = 0; r < 8; r++) { s0[r] = 0.f; s1[r] = 0.f; }
        #pragma unroll 4
        for (int d = 0; d < 64; d++) {
            float k0 = Kt[d * 65 + lane], k1 = Kt[d * 65 + lane + 32];
            #pragma unroll
            for (int r = 0; r < 8; r++) {
                float qv = Qs[(rb + r) * 64 + d];
                s0[r] = fmaf(qv, k0, s0[r]);
                s1[r] = fmaf(qv, k1, s1[r]);
            }
        }
        __syncthreads();

        int ig0 = qt * 64 + rb;
        int jg0 = jt * 64;
        #pragma unroll
        for (int r = 0; r < 8; r++) {
            int ig = ig0 + r;
            float x0 = tanhf(s0[r] * 0.02f) * 6.25f;
            float x1 = tanhf(s1[r] * 0.02f) * 6.25f;
            if (jg0 + lane      > ig) x0 = -3.0e38f;
            if (jg0 + lane + 32 > ig) x1 = -3.0e38f;
            float mx = fmaxf(x0, x1);
            #pragma unroll
            for (int o = 16; o; o >>= 1) mx = fmaxf(mx, __shfl_xor_sync(~0u, mx, o));
            float mn = fmaxf(m[r], mx);
            float alpha = __expf(m[r] - mn);
            float p0 = __expf(x0 - mn), p1 = __expf(x1 - mn);
            float ps = p0 + p1;
            #pragma unroll
            for (int o = 16; o; o >>= 1) ps += __shfl_xor_sync(~0u, ps, o);
            l[r] = l[r] * alpha + ps;
            m[r] = mn;
            a0[r] *= alpha;
            a1[r] *= alpha;
            Kt[(rb + r) * 65 + lane]      = p0;
            Kt[(rb + r) * 65 + lane + 32] = p1;
        }
        __syncwarp();

        #pragma unroll 4
        for (int jj = 0; jj < 64; jj++) {
            float v0 = Vs[jj * 64 + lane], v1 = Vs[jj * 64 + lane + 32];
            #pragma unroll
            for (int r = 0; r < 8; r++) {
                float p = Kt[(rb + r) * 65 + jj];
                a0[r] = fmaf(p, v0, a0[r]);
                a1[r] = fmaf(p, v1, a1[r]);
            }
        }
    }

    float* ob = g_oq + (((size_t)(b * QH_ + qh)) * NN + qt * 64 + rb) * DH_;
    #pragma unroll
    for (int r = 0; r < 8; r++) {
        float inv = 1.0f / l[r];
        ob[r * 64 + lane]      = a0[r] * inv;
        ob[r * 64 + lane + 32] = a1[r] * inv;
    }
}

// ---------------- group-sum -> fp16 ------------------------------------------
__global__ void combine_kernel() {
    int i = blockIdx.x * 256 + threadIdx.x;
    if (i >= BB * NN * HH * DH_) return;
    int d = i & 63;
    int h = (i >> 6) & 7;
    int bn = i >> 9;
    int n = bn & (NN - 1);
    int b = bn >> 11;
    size_t o0 = (((size_t)(b * QH_ + 2 * h)) * NN + n) * DH_ + d;
    size_t o1 = o0 + (size_t)NN * DH_;
    g_ah[i] = __float2half(g_oq[o0] + g_oq[o1]);
}

// ---------------- launch ------------------------------------------------------
extern "C" void kernel_launch(void* const* d_in, const int* in_sizes, int n_in,
                              void* d_out, int out_size) {
    const float* tokens  = (const float*)d_in[0];
    const float* norm_w  = (const float*)d_in[1];
    const float* Wq      = (const float*)d_in[2];
    const float* Wkv     = (const float*)d_in[3];
    const float* Wout    = (const float*)d_in[4];
    const float* q_gamma = (const float*)d_in[5];
    const float* k_gamma = (const float*)d_in[6];
    float* out = (float*)d_out;

    __half *xh, *wq, *wkv, *wo, *ah;
    float *q, *kv;
    cudaGetSymbolAddress((void**)&xh,  g_xh);
    cudaGetSymbolAddress((void**)&wq,  g_wq);
    cudaGetSymbolAddress((void**)&wkv, g_wkv);
    cudaGetSymbolAddress((void**)&wo,  g_wo);
    cudaGetSymbolAddress((void**)&ah,  g_ah);
    cudaGetSymbolAddress((void**)&q,   g_q);
    cudaGetSymbolAddress((void**)&kv,  g_kv);

    // weight transposes (fp32 -> fp16 [N][K])
    dim3 tb(32, 8);
    wtrans_kernel<<<dim3(32, 32), tb>>>(Wq,  wq,  1024, 1024);
    wtrans_kernel<<<dim3(32, 32), tb>>>(Wkv, wkv, 1024, 1024);
    wtrans_kernel<<<dim3(32, 16), tb>>>(Wout, wo,  512, 1024);

    // rmsnorm -> fp16
    rmsnorm_kernel<<<MM, 256>>>(tokens, norm_w);

    // projections (tensor core)
    dim3 ggrid(8, 32);
    hgemm_kernel<<<ggrid, 256>>>(xh, wq,  q,  1024);
    hgemm_kernel<<<ggrid, 256>>>(xh, wkv, kv, 1024);

    // per-head norms + v transpose
    qnorm_kernel<<<(MM * QH_ * 32) / 256, 256>>>(q_gamma);
    kvnorm_kernel<<<(MM * HH * 32) / 256, 256>>>(k_gamma);

    // attention
    int smem = (4096 + 64 * 65 + 4096) * sizeof(float);
    cudaFuncSetAttribute(attn_kernel, cudaFuncAttributeMaxDynamicSharedMemorySize, smem);
    dim3 agrid(NN / 64, QH_, BB);
    attn_kernel<<<agrid, 256, smem>>>();

    // group sum -> fp16, then output projection (tensor core)
    combine_kernel<<<(MM * HH * DH_) / 256, 256>>>();
    hgemm_kernel<<<ggrid, 256>>>(ah, wo, out, 512);
}

// round 4
// speedup vs baseline: 4.9666x; 3.0757x over previous
#include <cuda_runtime.h>
#include <cuda_fp16.h>
#include <cstdint>
#include <math.h>

#define BB 2
#define NN 2048
#define DD 1024
#define HH 8
#define QH_ 16
#define DH_ 64
#define MM (BB*NN)

// ---------------- scratch ----------------------------------------------------
__device__ __half g_xh [MM*DD];          // rmsnorm(x), fp16      [4096][1024]
__device__ __half g_wq [DD*DD];          // Wq^T  fp16 [n][k]
__device__ __half g_wkv[DD*DD];          // Wkv^T fp16 [n][k]
__device__ __half g_wo [DD*HH*DH_];      // Wout^T fp16 [n][k]
__device__ float  g_q  [MM*QH_*DH_];     // x@Wq   (fp32 gemm out)
__device__ float  g_kv [MM*2*HH*DH_];    // x@Wkv
__device__ __half g_qh [BB*QH_*NN*DH_];  // normalized q fp16 [b][qh][n][dh]
__device__ __half g_kh [BB*HH*NN*DH_];   // normalized k fp16 [b][h][n][dh]
__device__ __half g_vh [BB*HH*NN*DH_];   // v fp16           [b][h][n][dh]
__device__ __half g_ah [MM*HH*DH_];      // group-summed attn out fp16 [4096][512]

// ---------------- mma / ldmatrix helpers -------------------------------------
__device__ __forceinline__ void ldsm4(unsigned& r0, unsigned& r1, unsigned& r2,
                                      unsigned& r3, unsigned addr) {
    asm volatile("ldmatrix.sync.aligned.m8n8.x4.shared.b16 {%0,%1,%2,%3}, [%4];"
                 : "=r"(r0), "=r"(r1), "=r"(r2), "=r"(r3) : "r"(addr));
}
__device__ __forceinline__ void ldsm4t(unsigned& r0, unsigned& r1, unsigned& r2,
                                       unsigned& r3, unsigned addr) {
    asm volatile("ldmatrix.sync.aligned.m8n8.x4.trans.shared.b16 {%0,%1,%2,%3}, [%4];"
                 : "=r"(r0), "=r"(r1), "=r"(r2), "=r"(r3) : "r"(addr));
}
__device__ __forceinline__ void mma16816(float* c, const unsigned* a,
                                         unsigned b0, unsigned b1) {
    asm volatile(
        "mma.sync.aligned.m16n8k16.row.col.f32.f16.f16.f32 "
        "{%0,%1,%2,%3},{%4,%5,%6,%7},{%8,%9},{%0,%1,%2,%3};"
        : "+f"(c[0]), "+f"(c[1]), "+f"(c[2]), "+f"(c[3])
        : "r"(a[0]), "r"(a[1]), "r"(a[2]), "r"(a[3]), "r"(b0), "r"(b1));
}

// ---------------- rmsnorm -> fp16 --------------------------------------------
__global__ void rmsnorm_kernel(const float* __restrict__ x,
                               const float* __restrict__ w) {
    int row = blockIdx.x;
    const float* xr = x + (size_t)row * DD;
    float ss = 0.f;
    for (int i = threadIdx.x; i < DD; i += 256) { float v = xr[i]; ss = fmaf(v, v, ss); }
    __shared__ float red[8];
    #pragma unroll
    for (int o = 16; o; o >>= 1) ss += __shfl_xor_sync(~0u, ss, o);
    if ((threadIdx.x & 31) == 0) red[threadIdx.x >> 5] = ss;
    __syncthreads();
    if (threadIdx.x < 8) {
        ss = red[threadIdx.x];
        #pragma unroll
        for (int o = 4; o; o >>= 1) ss += __shfl_xor_sync(0xff, ss, o);
        if (threadIdx.x == 0) red[0] = ss;
    }
    __syncthreads();
    float r = rsqrtf(red[0] * (1.0f / DD) + 1.1920929e-07f);
    __half* yr = g_xh + (size_t)row * DD;
    for (int i = threadIdx.x; i < DD; i += 256) yr[i] = __float2half(xr[i] * r * w[i]);
}

// ---------------- weight transpose+convert: W[K][N] f32 -> Wt[N][K] f16 ------
__global__ void wtrans_kernel(const float* __restrict__ W, __half* __restrict__ Wt,
                              int K, int N) {
    __shared__ float t[32][33];
    int n0 = blockIdx.x * 32, k0 = blockIdx.y * 32;
    int x = threadIdx.x, y = threadIdx.y;
    #pragma unroll
    for (int i = 0; i < 32; i += 8)
        t[y + i][x] = W[(size_t)(k0 + y + i) * N + n0 + x];
    __syncthreads();
    #pragma unroll
    for (int i = 0; i < 32; i += 8)
        Wt[(size_t)(n0 + y + i) * K + k0 + x] = __float2half(t[x][y + i]);
}

// ---------------- fp16 tensor-core GEMM: C[M][1024] = A[M][K] @ Bt[N][K]^T ---
#define ASTR 40
#define ABUF (128*ASTR)
__global__ void __launch_bounds__(256, 2)
hgemm_kernel(const __half* __restrict__ A, const __half* __restrict__ Bt,
             float* __restrict__ C, int K) {
    __shared__ __half sh[4 * ABUF];
    const int tid = threadIdx.x;
    const int lane = tid & 31;
    const int warp = tid >> 5;
    const int wm = (warp >> 1) << 5;
    const int wn = (warp & 1) << 6;
    const int bm = blockIdx.y << 7;
    const int bn = blockIdx.x << 7;

    const int lr = tid >> 2;
    const int lg = (tid & 3) << 3;
    const __half* Ag = A + (size_t)(bm + lr) * K + lg;
    const __half* Bg = Bt + (size_t)(bn + lr) * K + lg;
    const size_t rowskip = (size_t)64 * K;

    unsigned sb;
    asm("{ .reg .u64 t; cvta.to.shared.u64 t, %1; cvt.u32.u64 %0, t; }"
        : "=r"(sb) : "l"(sh));
    const int aRow = wm + (lane & 15);
    const int aK   = (lane >> 4) << 3;
    const int bRow = wn + (lane & 7) + ((lane >> 4) << 3);
    const int bK   = ((lane >> 3) & 1) << 3;
    const unsigned ldA = sb + (unsigned)(aRow * ASTR + aK) * 2u;
    const unsigned ldB = sb + (unsigned)(2 * ABUF + bRow * ASTR + bK) * 2u;

    float acc[2][8][4];
    #pragma unroll
    for (int i = 0; i < 2; i++) {
        #pragma unroll
        for (int j = 0; j < 8; j++) {
            #pragma unroll
            for (int q = 0; q < 4; q++) acc[i][j][q] = 0.f;
        }
    }

    uint4 pa0 = *(const uint4*)Ag;
    uint4 pa1 = *(const uint4*)(Ag + rowskip);
    uint4 pb0 = *(const uint4*)Bg;
    uint4 pb1 = *(const uint4*)(Bg + rowskip);
    {
        __half* as = sh + lr * ASTR + lg;
        __half* bs = sh + 2 * ABUF + lr * ASTR + lg;
        *(uint4*)as = pa0;
        *(uint4*)(as + 64 * ASTR) = pa1;
        *(uint4*)bs = pb0;
        *(uint4*)(bs + 64 * ASTR) = pb1;
    }
    __syncthreads();

    const int nch = K >> 5;
    for (int c = 0; c < nch; c++) {
        if (c + 1 < nch) {
            const __half* An = Ag + (c + 1) * 32;
            const __half* Bn = Bg + (c + 1) * 32;
            pa0 = *(const uint4*)An;
            pa1 = *(const uint4*)(An + rowskip);
            pb0 = *(const uint4*)Bn;
            pb1 = *(const uint4*)(Bn + rowskip);
        }
        const unsigned bo = (unsigned)(c & 1) * (unsigned)(ABUF * 2);
        #pragma unroll
        for (int ks = 0; ks < 2; ks++) {
            unsigned a0r[4], a1r[4], b[4][4];
            ldsm4(a0r[0], a0r[1], a0r[2], a0r[3], ldA + bo + ks * 32);
            ldsm4(a1r[0], a1r[1], a1r[2], a1r[3],
                  ldA + bo + 16 * ASTR * 2 + ks * 32);
            #pragma unroll
            for (int p = 0; p < 4; p++)
                ldsm4(b[p][0], b[p][1], b[p][2], b[p][3],
                      ldB + bo + (unsigned)(p * 16 * ASTR * 2) + ks * 32);
            #pragma unroll
            for (int p = 0; p < 4; p++) {
                mma16816(acc[0][2 * p],     a0r, b[p][0], b[p][1]);
                mma16816(acc[0][2 * p + 1], a0r, b[p][2], b[p][3]);
                mma16816(acc[1][2 * p],     a1r, b[p][0], b[p][1]);
                mma16816(acc[1][2 * p + 1], a1r, b[p][2], b[p][3]);
            }
        }
        if (c + 1 < nch) {
            __syncthreads();
            __half* as = sh + ((c + 1) & 1) * ABUF + lr * ASTR + lg;
            __half* bs = as + 2 * ABUF;
            *(uint4*)as = pa0;
            *(uint4*)(as + 64 * ASTR) = pa1;
            *(uint4*)bs = pb0;
            *(uint4*)(bs + 64 * ASTR) = pb1;
            __syncthreads();
        }
    }

    const int er = lane >> 2;
    const int ec = (lane & 3) << 1;
    #pragma unroll
    for (int mt = 0; mt < 2; mt++) {
        #pragma unroll
        for (int nt = 0; nt < 8; nt++) {
            int r0 = bm + wm + mt * 16 + er;
            int c0 = bn + wn + nt * 8 + ec;
            *(float2*)&C[(size_t)r0 * 1024 + c0] =
                make_float2(acc[mt][nt][0], acc[mt][nt][1]);
            *(float2*)&C[(size_t)(r0 + 8) * 1024 + c0] =
                make_float2(acc[mt][nt][2], acc[mt][nt][3]);
        }
    }
}

// ---------------- per-head l2norm * (gamma+1)*sqrt(dh) -> fp16 ---------------
__global__ void qnorm_kernel(const float* __restrict__ gamma) {
    int gw = (blockIdx.x * 256 + threadIdx.x) >> 5;
    int lane = threadIdx.x & 31;
    if (gw >= BB * NN * QH_) return;
    int qh = gw % QH_;
    int bn = gw / QH_;
    int n = bn % NN, b = bn / NN;
    const float* src = g_q + ((size_t)bn * QH_ + qh) * DH_;
    float v0 = src[lane], v1 = src[lane + 32];
    float ss = v0 * v0 + v1 * v1;
    #pragma unroll
    for (int o = 16; o; o >>= 1) ss += __shfl_xor_sync(~0u, ss, o);
    float inv = 1.0f / fmaxf(sqrtf(ss), 1e-12f);
    float g0 = (gamma[qh * DH_ + lane] + 1.f) * 8.f;
    float g1 = (gamma[qh * DH_ + lane + 32] + 1.f) * 8.f;
    __half* dst = g_qh + (((size_t)(b * QH_ + qh)) * NN + n) * DH_;
    dst[lane]      = __float2half(v0 * inv * g0);
    dst[lane + 32] = __float2half(v1 * inv * g1);
}

__global__ void kvnorm_kernel(const float* __restrict__ gamma) {
    int gw = (blockIdx.x * 256 + threadIdx.x) >> 5;
    int lane = threadIdx.x & 31;
    if (gw >= BB * NN * HH) return;
    int h = gw % HH;
    int bn = gw / HH;
    int n = bn % NN, b = bn / NN;
    const float* ksrc = g_kv + (size_t)bn * (2 * HH * DH_) + h * DH_;
    const float* vsrc = ksrc + HH * DH_;
    float v0 = ksrc[lane], v1 = ksrc[lane + 32];
    float ss = v0 * v0 + v1 * v1;
    #pragma unroll
    for (int o = 16; o; o >>= 1) ss += __shfl_xor_sync(~0u, ss, o);
    float inv = 1.0f / fmaxf(sqrtf(ss), 1e-12f);
    float g0 = (gamma[h * DH_ + lane] + 1.f) * 8.f;
    float g1 = (gamma[h * DH_ + lane + 32] + 1.f) * 8.f;
    size_t base = (((size_t)(b * HH + h)) * NN + n) * DH_;
    g_kh[base + lane]      = __float2half(v0 * inv * g0);
    g_kh[base + lane + 32] = __float2half(v1 * inv * g1);
    g_vh[base + lane]      = __float2half(vsrc[lane]);
    g_vh[base + lane + 32] = __float2half(vsrc[lane + 32]);
}

// ---------------- tensor-core flash attention, causal + tanh softcap ---------
// grid (N/64, HH, BB), 256 threads = 8 warps.
// warps 0-3: query head 2h, warps 4-7: query head 2h+1; 16 q-rows per warp.
// smem halves: Qs[2][64][72] @0, Ks[64][72] @9216, Vs[64][72] @13824.
// After the j-loop, Ks+Vs region is reused as float Obuf[64][66].
#define TSTR 72
__global__ void __launch_bounds__(256) attn_kernel() {
    __shared__ __half sh[(2 * 64 + 64 + 64) * TSTR];   // 36864 B
    float* Obuf = (float*)(sh + 9216);
    const int qt = blockIdx.x, h = blockIdx.y, b = blockIdx.z;
    const int tid = threadIdx.x, lane = tid & 31, warp = tid >> 5;
    const int hw = warp >> 2;            // group head (0/1)
    const int wr = (warp & 3) << 4;      // row offset within 64
    const int er = lane >> 2, ec = (lane & 3) << 1;

    // load Q for both heads
    const __half* qg = g_qh + (((size_t)(b * QH_ + 2 * h)) * NN + qt * 64) * DH_;
    #pragma unroll
    for (int it = 0; it < 4; it++) {
        int u = tid + it * 256;
        int head = u >> 9, row = (u >> 3) & 63, cg = u & 7;
        *(uint4*)(sh + head * 4608 + row * TSTR + cg * 8) =
            *(const uint4*)(qg + (size_t)head * NN * DH_ + row * 64 + cg * 8);
    }

    unsigned sb;
    asm("{ .reg .u64 t; cvta.to.shared.u64 t, %1; cvt.u32.u64 %0, t; }"
        : "=r"(sb) : "l"(sh));
    const unsigned ldQ = sb + (unsigned)(hw * 4608 + (wr + (lane & 15)) * TSTR
                                         + ((lane >> 4) << 3)) * 2u;
    const unsigned ldK = sb + (unsigned)(9216 + ((lane & 7) + ((lane >> 4) << 3)) * TSTR
                                         + (((lane >> 3) & 1) << 3)) * 2u;
    const unsigned ldV = sb + (unsigned)(13824 + ((lane & 7) + (((lane >> 3) & 1) << 3)) * TSTR
                                         + ((lane >> 4) << 3)) * 2u;

    const __half* kg = g_kh + ((size_t)(b * HH + h)) * NN * DH_;
    const __half* vg = g_vh + ((size_t)(b * HH + h)) * NN * DH_;

    float ofrag[8][4];
    float mrow[2] = {-3.0e38f, -3.0e38f};
    float lrow[2] = {0.f, 0.f};
    #pragma unroll
    for (int nt = 0; nt < 8; nt++) {
        #pragma unroll
        for (int q = 0; q < 4; q++) ofrag[nt][q] = 0.f;
    }

    for (int jt = 0; jt <= qt; jt++) {
        __syncthreads();
        #pragma unroll
        for (int it = 0; it < 2; it++) {
            int u = tid + it * 256;
            int row = u >> 3, cg = u & 7;
            size_t go = (size_t)(jt * 64 + row) * 64 + cg * 8;
            *(uint4*)(sh + 9216 + row * TSTR + cg * 8)  = *(const uint4*)(kg + go);
            *(uint4*)(sh + 13824 + row * TSTR + cg * 8) = *(const uint4*)(vg + go);
        }
        __syncthreads();

        // ---- S = Q @ K^T ----
        float sfrag[8][4];
        #pragma unroll
        for (int nt = 0; nt < 8; nt++) {
            #pragma unroll
            for (int q = 0; q < 4; q++) sfrag[nt][q] = 0.f;
        }
        #pragma unroll
        for (int ks = 0; ks < 4; ks++) {
            unsigned a[4];
            ldsm4(a[0], a[1], a[2], a[3], ldQ + ks * 32);
            #pragma unroll
            for (int np = 0; np < 4; np++) {
                unsigned bf[4];
                ldsm4(bf[0], bf[1], bf[2], bf[3],
                      ldK + (unsigned)(np * 16 * TSTR * 2) + ks * 32);
                mma16816(sfrag[2 * np],     a, bf[0], bf[1]);
                mma16816(sfrag[2 * np + 1], a, bf[2], bf[3]);
            }
        }

        // ---- softcap + mask + online softmax ----
        const bool diag = (jt == qt);
        #pragma unroll
        for (int r2 = 0; r2 < 2; r2++) {
            const int ig = wr + er + 8 * r2;        // tile-local row
            float mx = -3.0e38f;
            #pragma unroll
            for (int nt = 0; nt < 8; nt++) {
                #pragma unroll
                for (int c = 0; c < 2; c++) {
                    float x = tanhf(sfrag[nt][2 * r2 + c] * 0.02f) * 6.25f;
                    if (diag && (nt * 8 + ec + c > ig)) x = -3.0e38f;
                    sfrag[nt][2 * r2 + c] = x;
                    mx = fmaxf(mx, x);
                }
            }
            mx = fmaxf(mx, __shfl_xor_sync(~0u, mx, 1));
            mx = fmaxf(mx, __shfl_xor_sync(~0u, mx, 2));
            float mn = fmaxf(mrow[r2], mx);
            float alpha = __expf(mrow[r2] - mn);
            mrow[r2] = mn;
            float ps = 0.f;
            #pragma unroll
            for (int nt = 0; nt < 8; nt++) {
                #pragma unroll
                for (int c = 0; c < 2; c++) {
                    float p = __expf(sfrag[nt][2 * r2 + c] - mn);
                    sfrag[nt][2 * r2 + c] = p;
                    ps += p;
                }
            }
            ps += __shfl_xor_sync(~0u, ps, 1);
            ps += __shfl_xor_sync(~0u, ps, 2);
            lrow[r2] = lrow[r2] * alpha + ps;
            #pragma unroll
            for (int nt = 0; nt < 8; nt++) {
                ofrag[nt][2 * r2]     *= alpha;
                ofrag[nt][2 * r2 + 1] *= alpha;
            }
        }

        // pack P to fp16 a-fragments
        unsigned pa[8][2];
        #pragma unroll
        for (int nt = 0; nt < 8; nt++) {
            __half2 h0 = __floats2half2_rn(sfrag[nt][0], sfrag[nt][1]);
            __half2 h1 = __floats2half2_rn(sfrag[nt][2], sfrag[nt][3]);
            pa[nt][0] = *(unsigned*)&h0;
            pa[nt][1] = *(unsigned*)&h1;
        }

        // ---- O += P @ V ----
        #pragma unroll
        for (int kv = 0; kv < 4; kv++) {
            unsigned a[4] = {pa[2 * kv][0], pa[2 * kv][1],
                             pa[2 * kv + 1][0], pa[2 * kv + 1][1]};
            #pragma unroll
            for (int np = 0; np < 4; np++) {
                unsigned bf[4];
                ldsm4t(bf[0], bf[1], bf[2], bf[3],
                       ldV + (unsigned)(kv * 16 * TSTR * 2) + np * 32);
                mma16816(ofrag[2 * np],     a, bf[0], bf[1]);
                mma16816(ofrag[2 * np + 1], a, bf[2], bf[3]);
            }
        }
    }

    // ---- combine group heads + write fp16 ----
    const float inv0 = 1.0f / lrow[0];
    const float inv1 = 1.0f / lrow[1];
    __syncthreads();                         // done with Vs before Obuf reuse
    if (hw == 1) {
        #pragma unroll
        for (int nt = 0; nt < 8; nt++) {
            Obuf[(wr + er) * 66 + nt * 8 + ec]         = ofrag[nt][0] * inv0;
            Obuf[(wr + er) * 66 + nt * 8 + ec + 1]     = ofrag[nt][1] * inv0;
            Obuf[(wr + er + 8) * 66 + nt * 8 + ec]     = ofrag[nt][2] * inv1;
            Obuf[(wr + er + 8) * 66 + nt * 8 + ec + 1] = ofrag[nt][3] * inv1;
        }
    }
    __syncthreads();
    if (hw == 0) {
        size_t gr0 = (size_t)(b * NN + qt * 64 + wr + er) * (HH * DH_) + h * DH_;
        size_t gr1 = gr0 + 8 * (HH * DH_);
        #pragma unroll
        for (int nt = 0; nt < 8; nt++) {
            float o0 = ofrag[nt][0] * inv0 + Obuf[(wr + er) * 66 + nt * 8 + ec];
            float o1 = ofrag[nt][1] * inv0 + Obuf[(wr + er) * 66 + nt * 8 + ec + 1];
            float o2 = ofrag[nt][2] * inv1 + Obuf[(wr + er + 8) * 66 + nt * 8 + ec];
            float o3 = ofrag[nt][3] * inv1 + Obuf[(wr + er + 8) * 66 + nt * 8 + ec + 1];
            *(__half2*)(g_ah + gr0 + nt * 8 + ec) = __floats2half2_rn(o0, o1);
            *(__half2*)(g_ah + gr1 + nt * 8 + ec) = __floats2half2_rn(o2, o3);
        }
    }
}

// ---------------- launch ------------------------------------------------------
extern "C" void kernel_launch(void* const* d_in, const int* in_sizes, int n_in,
                              void* d_out, int out_size) {
    const float* tokens  = (const float*)d_in[0];
    const float* norm_w  = (const float*)d_in[1];
    const float* Wq      = (const float*)d_in[2];
    const float* Wkv     = (const float*)d_in[3];
    const float* Wout    = (const float*)d_in[4];
    const float* q_gamma = (const float*)d_in[5];
    const float* k_gamma = (const float*)d_in[6];
    float* out = (float*)d_out;

    __half *xh, *wq, *wkv, *wo, *ah;
    float *q, *kv;
    cudaGetSymbolAddress((void**)&xh,  g_xh);
    cudaGetSymbolAddress((void**)&wq,  g_wq);
    cudaGetSymbolAddress((void**)&wkv, g_wkv);
    cudaGetSymbolAddress((void**)&wo,  g_wo);
    cudaGetSymbolAddress((void**)&ah,  g_ah);
    cudaGetSymbolAddress((void**)&q,   g_q);
    cudaGetSymbolAddress((void**)&kv,  g_kv);

    // weight transposes (fp32 -> fp16 [N][K])
    dim3 tb(32, 8);
    wtrans_kernel<<<dim3(32, 32), tb>>>(Wq,  wq,  1024, 1024);
    wtrans_kernel<<<dim3(32, 32), tb>>>(Wkv, wkv, 1024, 1024);
    wtrans_kernel<<<dim3(32, 16), tb>>>(Wout, wo,  512, 1024);

    // rmsnorm -> fp16
    rmsnorm_kernel<<<MM, 256>>>(tokens, norm_w);

    // projections (tensor core)
    dim3 ggrid(8, 32);
    hgemm_kernel<<<ggrid, 256>>>(xh, wq,  q,  1024);
    hgemm_kernel<<<ggrid, 256>>>(xh, wkv, kv, 1024);

    // per-head norms -> fp16
    qnorm_kernel<<<(MM * QH_ * 32) / 256, 256>>>(q_gamma);
    kvnorm_kernel<<<(MM * HH * 32) / 256, 256>>>(k_gamma);

    // tensor-core attention (group-summed, writes g_ah fp16 directly)
    dim3 agrid(NN / 64, HH, BB);
    attn_kernel<<<agrid, 256>>>();

    // output projection (tensor core)
    hgemm_kernel<<<ggrid, 256>>>(ah, wo, out, 512);
}

// round 5
// speedup vs baseline: 6.3183x; 1.2722x over previous
#include <cuda_runtime.h>
#include <cuda_fp16.h>
#include <cstdint>
#include <math.h>

#define BB 2
#define NN 2048
#define DD 1024
#define HH 8
#define QH_ 16
#define DH_ 64
#define MM (BB*NN)

// ---------------- scratch ----------------------------------------------------
__device__ __half g_xh [MM*DD];            // rmsnorm(x), fp16 [4096][1024]
__device__ __half g_w  [2*DD*DD];          // [Wq^T ; Wkv^T] fp16 [2048][1024]
__device__ __half g_wo [DD*HH*DH_];        // Wout^T fp16 [1024][512]
__device__ __half g_qh [BB*QH_*NN*DH_];    // normalized q fp16 [b][qh][n][dh]
__device__ __half g_kh [BB*HH*NN*DH_];     // normalized k fp16 [b][h][n][dh]
__device__ __half g_vh [BB*HH*NN*DH_];     // v fp16           [b][h][n][dh]
__device__ __half g_ah [MM*HH*DH_];        // group-summed attn out fp16 [4096][512]

// ---------------- mma / ldmatrix helpers -------------------------------------
__device__ __forceinline__ void ldsm4(unsigned& r0, unsigned& r1, unsigned& r2,
                                      unsigned& r3, unsigned addr) {
    asm volatile("ldmatrix.sync.aligned.m8n8.x4.shared.b16 {%0,%1,%2,%3}, [%4];"
                 : "=r"(r0), "=r"(r1), "=r"(r2), "=r"(r3) : "r"(addr));
}
__device__ __forceinline__ void ldsm4t(unsigned& r0, unsigned& r1, unsigned& r2,
                                       unsigned& r3, unsigned addr) {
    asm volatile("ldmatrix.sync.aligned.m8n8.x4.trans.shared.b16 {%0,%1,%2,%3}, [%4];"
                 : "=r"(r0), "=r"(r1), "=r"(r2), "=r"(r3) : "r"(addr));
}
__device__ __forceinline__ void mma16816(float* c, const unsigned* a,
                                         unsigned b0, unsigned b1) {
    asm volatile(
        "mma.sync.aligned.m16n8k16.row.col.f32.f16.f16.f32 "
        "{%0,%1,%2,%3},{%4,%5,%6,%7},{%8,%9},{%0,%1,%2,%3};"
        : "+f"(c[0]), "+f"(c[1]), "+f"(c[2]), "+f"(c[3])
        : "r"(a[0]), "r"(a[1]), "r"(a[2]), "r"(a[3]), "r"(b0), "r"(b1));
}

// ---------------- rmsnorm -> fp16 (vectorized) --------------------------------
__global__ void rmsnorm_kernel(const float* __restrict__ x,
                               const float* __restrict__ w) {
    int row = blockIdx.x;
    int tid = threadIdx.x;
    const float4 xv = ((const float4*)(x + (size_t)row * DD))[tid];
    float ss = xv.x * xv.x + xv.y * xv.y + xv.z * xv.z + xv.w * xv.w;
    __shared__ float red[8];
    #pragma unroll
    for (int o = 16; o; o >>= 1) ss += __shfl_xor_sync(~0u, ss, o);
    if ((tid & 31) == 0) red[tid >> 5] = ss;
    __syncthreads();
    if (tid < 8) {
        ss = red[tid];
        #pragma unroll
        for (int o = 4; o; o >>= 1) ss += __shfl_xor_sync(0xff, ss, o);
        if (tid == 0) red[0] = ss;
    }
    __syncthreads();
    float r = rsqrtf(red[0] * (1.0f / DD) + 1.1920929e-07f);
    const float4 wv = ((const float4*)w)[tid];
    __half2 h0 = __floats2half2_rn(xv.x * r * wv.x, xv.y * r * wv.y);
    __half2 h1 = __floats2half2_rn(xv.z * r * wv.z, xv.w * r * wv.w);
    __half2* yr = (__half2*)(g_xh + (size_t)row * DD);
    yr[2 * tid]     = h0;
    yr[2 * tid + 1] = h1;
}

// ---------------- weight transpose+convert: W[K][N] f32 -> Wt[N][K] f16 ------
__global__ void wtrans_kernel(const float* __restrict__ W, __half* __restrict__ Wt,
                              int K, int N) {
    __shared__ float t[32][33];
    int n0 = blockIdx.x * 32, k0 = blockIdx.y * 32;
    int x = threadIdx.x, y = threadIdx.y;
    #pragma unroll
    for (int i = 0; i < 32; i += 8)
        t[y + i][x] = W[(size_t)(k0 + y + i) * N + n0 + x];
    __syncthreads();
    #pragma unroll
    for (int i = 0; i < 32; i += 8)
        Wt[(size_t)(n0 + y + i) * K + k0 + x] = __float2half(t[x][y + i]);
}

#define ASTR 40
#define ABUF (128*ASTR)

// ---------------- fused QKV GEMM + per-head norm epilogue --------------------
// C = xh[4096][1024] @ g_w[2048][1024]^T ; cols 0-1023 q, 1024-1535 k, 1536-2047 v.
// Epilogue: q,k -> l2norm * (gamma+1)*8 -> g_qh/g_kh fp16; v -> g_vh fp16.
__global__ void __launch_bounds__(256, 2)
qkv_gemm_kernel(const __half* __restrict__ A, const __half* __restrict__ Bt,
                const float* __restrict__ q_gamma,
                const float* __restrict__ k_gamma) {
    __shared__ __half sh[4 * ABUF];
    const int K = 1024;
    const int tid = threadIdx.x;
    const int lane = tid & 31;
    const int warp = tid >> 5;
    const int wm = (warp >> 1) << 5;
    const int wn = (warp & 1) << 6;
    const int bm = blockIdx.y << 7;
    const int bn = blockIdx.x << 7;

    const int lr = tid >> 2;
    const int lg = (tid & 3) << 3;
    const __half* Ag = A + (size_t)(bm + lr) * K + lg;
    const __half* Bg = Bt + (size_t)(bn + lr) * K + lg;
    const size_t rowskip = (size_t)64 * K;

    unsigned sb;
    asm("{ .reg .u64 t; cvta.to.shared.u64 t, %1; cvt.u32.u64 %0, t; }"
        : "=r"(sb) : "l"(sh));
    const int aRow = wm + (lane & 15);
    const int aK   = (lane >> 4) << 3;
    const int bRow = wn + (lane & 7) + ((lane >> 4) << 3);
    const int bK   = ((lane >> 3) & 1) << 3;
    const unsigned ldA = sb + (unsigned)(aRow * ASTR + aK) * 2u;
    const unsigned ldB = sb + (unsigned)(2 * ABUF + bRow * ASTR + bK) * 2u;

    float acc[2][8][4];
    #pragma unroll
    for (int i = 0; i < 2; i++) {
        #pragma unroll
        for (int j = 0; j < 8; j++) {
            #pragma unroll
            for (int q = 0; q < 4; q++) acc[i][j][q] = 0.f;
        }
    }

    uint4 pa0 = *(const uint4*)Ag;
    uint4 pa1 = *(const uint4*)(Ag + rowskip);
    uint4 pb0 = *(const uint4*)Bg;
    uint4 pb1 = *(const uint4*)(Bg + rowskip);
    {
        __half* as = sh + lr * ASTR + lg;
        __half* bs = sh + 2 * ABUF + lr * ASTR + lg;
        *(uint4*)as = pa0;
        *(uint4*)(as + 64 * ASTR) = pa1;
        *(uint4*)bs = pb0;
        *(uint4*)(bs + 64 * ASTR) = pb1;
    }
    __syncthreads();

    const int nch = K >> 5;
    for (int c = 0; c < nch; c++) {
        if (c + 1 < nch) {
            const __half* An = Ag + (c + 1) * 32;
            const __half* Bn = Bg + (c + 1) * 32;
            pa0 = *(const uint4*)An;
            pa1 = *(const uint4*)(An + rowskip);
            pb0 = *(const uint4*)Bn;
            pb1 = *(const uint4*)(Bn + rowskip);
        }
        const unsigned bo = (unsigned)(c & 1) * (unsigned)(ABUF * 2);
        #pragma unroll
        for (int ks = 0; ks < 2; ks++) {
            unsigned a0r[4], a1r[4], b[4][4];
            ldsm4(a0r[0], a0r[1], a0r[2], a0r[3], ldA + bo + ks * 32);
            ldsm4(a1r[0], a1r[1], a1r[2], a1r[3],
                  ldA + bo + 16 * ASTR * 2 + ks * 32);
            #pragma unroll
            for (int p = 0; p < 4; p++)
                ldsm4(b[p][0], b[p][1], b[p][2], b[p][3],
                      ldB + bo + (unsigned)(p * 16 * ASTR * 2) + ks * 32);
            #pragma unroll
            for (int p = 0; p < 4; p++) {
                mma16816(acc[0][2 * p],     a0r, b[p][0], b[p][1]);
                mma16816(acc[0][2 * p + 1], a0r, b[p][2], b[p][3]);
                mma16816(acc[1][2 * p],     a1r, b[p][0], b[p][1]);
                mma16816(acc[1][2 * p + 1], a1r, b[p][2], b[p][3]);
            }
        }
        if (c + 1 < nch) {
            __syncthreads();
            __half* as = sh + ((c + 1) & 1) * ABUF + lr * ASTR + lg;
            __half* bs = as + 2 * ABUF;
            *(uint4*)as = pa0;
            *(uint4*)(as + 64 * ASTR) = pa1;
            *(uint4*)bs = pb0;
            *(uint4*)(bs + 64 * ASTR) = pb1;
            __syncthreads();
        }
    }

    // ---- fused epilogue: per-head l2norm / convert ----
    const int er = lane >> 2;
    const int ec = (lane & 3) << 1;
    const int colbase = bn + wn;             // multiple of 64 == one head
    int head, nh;
    __half* darr;
    const float* gp;
    if (colbase < 1024)      { head = colbase >> 6;          darr = g_qh; gp = q_gamma + head * 64; nh = 16; }
    else if (colbase < 1536) { head = (colbase - 1024) >> 6; darr = g_kh; gp = k_gamma + head * 64; nh = 8; }
    else                     { head = (colbase - 1536) >> 6; darr = g_vh; gp = nullptr;             nh = 8; }

    float gs[8][2];
    #pragma unroll
    for (int nt = 0; nt < 8; nt++) {
        if (gp) {
            gs[nt][0] = (gp[nt * 8 + ec] + 1.f) * 8.f;
            gs[nt][1] = (gp[nt * 8 + ec + 1] + 1.f) * 8.f;
        } else {
            gs[nt][0] = 1.f;
            gs[nt][1] = 1.f;
        }
    }

    #pragma unroll
    for (int mt = 0; mt < 2; mt++) {
        #pragma unroll
        for (int rh = 0; rh < 2; rh++) {
            float s = 0.f;
            #pragma unroll
            for (int nt = 0; nt < 8; nt++) {
                float v0 = acc[mt][nt][2 * rh];
                float v1 = acc[mt][nt][2 * rh + 1];
                s = fmaf(v0, v0, fmaf(v1, v1, s));
            }
            s += __shfl_xor_sync(~0u, s, 1);
            s += __shfl_xor_sync(~0u, s, 2);
            float iv = gp ? (1.0f / fmaxf(sqrtf(s), 1e-12f)) : 1.0f;

            int m = bm + wm + mt * 16 + rh * 8 + er;
            int b = m >> 11, n = m & (NN - 1);
            __half* drow = darr + (((size_t)(b * nh + head)) * NN + n) * DH_;
            #pragma unroll
            for (int nt = 0; nt < 8; nt++) {
                float o0 = acc[mt][nt][2 * rh] * iv * gs[nt][0];
                float o1 = acc[mt][nt][2 * rh + 1] * iv * gs[nt][1];
                *(__half2*)(drow + nt * 8 + ec) = __floats2half2_rn(o0, o1);
            }
        }
    }
}

// ---------------- out-proj GEMM: out[4096][1024] = ah @ wo^T (fp32 out) ------
__global__ void __launch_bounds__(256, 2)
hgemm_kernel(const __half* __restrict__ A, const __half* __restrict__ Bt,
             float* __restrict__ C, int K) {
    __shared__ __half sh[4 * ABUF];
    const int tid = threadIdx.x;
    const int lane = tid & 31;
    const int warp = tid >> 5;
    const int wm = (warp >> 1) << 5;
    const int wn = (warp & 1) << 6;
    const int bm = blockIdx.y << 7;
    const int bn = blockIdx.x << 7;

    const int lr = tid >> 2;
    const int lg = (tid & 3) << 3;
    const __half* Ag = A + (size_t)(bm + lr) * K + lg;
    const __half* Bg = Bt + (size_t)(bn + lr) * K + lg;
    const size_t rowskip = (size_t)64 * K;

    unsigned sb;
    asm("{ .reg .u64 t; cvta.to.shared.u64 t, %1; cvt.u32.u64 %0, t; }"
        : "=r"(sb) : "l"(sh));
    const int aRow = wm + (lane & 15);
    const int aK   = (lane >> 4) << 3;
    const int bRow = wn + (lane & 7) + ((lane >> 4) << 3);
    const int bK   = ((lane >> 3) & 1) << 3;
    const unsigned ldA = sb + (unsigned)(aRow * ASTR + aK) * 2u;
    const unsigned ldB = sb + (unsigned)(2 * ABUF + bRow * ASTR + bK) * 2u;

    float acc[2][8][4];
    #pragma unroll
    for (int i = 0; i < 2; i++) {
        #pragma unroll
        for (int j = 0; j < 8; j++) {
            #pragma unroll
            for (int q = 0; q < 4; q++) acc[i][j][q] = 0.f;
        }
    }

    uint4 pa0 = *(const uint4*)Ag;
    uint4 pa1 = *(const uint4*)(Ag + rowskip);
    uint4 pb0 = *(const uint4*)Bg;
    uint4 pb1 = *(const uint4*)(Bg + rowskip);
    {
        __half* as = sh + lr * ASTR + lg;
        __half* bs = sh + 2 * ABUF + lr * ASTR + lg;
        *(uint4*)as = pa0;
        *(uint4*)(as + 64 * ASTR) = pa1;
        *(uint4*)bs = pb0;
        *(uint4*)(bs + 64 * ASTR) = pb1;
    }
    __syncthreads();

    const int nch = K >> 5;
    for (int c = 0; c < nch; c++) {
        if (c + 1 < nch) {
            const __half* An = Ag + (c + 1) * 32;
            const __half* Bn = Bg + (c + 1) * 32;
            pa0 = *(const uint4*)An;
            pa1 = *(const uint4*)(An + rowskip);
            pb0 = *(const uint4*)Bn;
            pb1 = *(const uint4*)(Bn + rowskip);
        }
        const unsigned bo = (unsigned)(c & 1) * (unsigned)(ABUF * 2);
        #pragma unroll
        for (int ks = 0; ks < 2; ks++) {
            unsigned a0r[4], a1r[4], b[4][4];
            ldsm4(a0r[0], a0r[1], a0r[2], a0r[3], ldA + bo + ks * 32);
            ldsm4(a1r[0], a1r[1], a1r[2], a1r[3],
                  ldA + bo + 16 * ASTR * 2 + ks * 32);
            #pragma unroll
            for (int p = 0; p < 4; p++)
                ldsm4(b[p][0], b[p][1], b[p][2], b[p][3],
                      ldB + bo + (unsigned)(p * 16 * ASTR * 2) + ks * 32);
            #pragma unroll
            for (int p = 0; p < 4; p++) {
                mma16816(acc[0][2 * p],     a0r, b[p][0], b[p][1]);
                mma16816(acc[0][2 * p + 1], a0r, b[p][2], b[p][3]);
                mma16816(acc[1][2 * p],     a1r, b[p][0], b[p][1]);
                mma16816(acc[1][2 * p + 1], a1r, b[p][2], b[p][3]);
            }
        }
        if (c + 1 < nch) {
            __syncthreads();
            __half* as = sh + ((c + 1) & 1) * ABUF + lr * ASTR + lg;
            __half* bs = as + 2 * ABUF;
            *(uint4*)as = pa0;
            *(uint4*)(as + 64 * ASTR) = pa1;
            *(uint4*)bs = pb0;
            *(uint4*)(bs + 64 * ASTR) = pb1;
            __syncthreads();
        }
    }

    const int er = lane >> 2;
    const int ec = (lane & 3) << 1;
    #pragma unroll
    for (int mt = 0; mt < 2; mt++) {
        #pragma unroll
        for (int nt = 0; nt < 8; nt++) {
            int r0 = bm + wm + mt * 16 + er;
            int c0 = bn + wn + nt * 8 + ec;
            *(float2*)&C[(size_t)r0 * 1024 + c0] =
                make_float2(acc[mt][nt][0], acc[mt][nt][1]);
            *(float2*)&C[(size_t)(r0 + 8) * 1024 + c0] =
                make_float2(acc[mt][nt][2], acc[mt][nt][3]);
        }
    }
}

// ---------------- tensor-core flash attention, causal + tanh softcap ---------
#define TSTR 72
__global__ void __launch_bounds__(256) attn_kernel() {
    __shared__ __half sh[(2 * 64 + 64 + 64) * TSTR];   // 36864 B
    float* Obuf = (float*)(sh + 9216);
    const int qt = 31 - blockIdx.x;          // heavy tiles first
    const int h = blockIdx.y, b = blockIdx.z;
    const int tid = threadIdx.x, lane = tid & 31, warp = tid >> 5;
    const int hw = warp >> 2;
    const int wr = (warp & 3) << 4;
    const int er = lane >> 2, ec = (lane & 3) << 1;

    const __half* qg = g_qh + (((size_t)(b * QH_ + 2 * h)) * NN + qt * 64) * DH_;
    #pragma unroll
    for (int it = 0; it < 4; it++) {
        int u = tid + it * 256;
        int head = u >> 9, row = (u >> 3) & 63, cg = u & 7;
        *(uint4*)(sh + head * 4608 + row * TSTR + cg * 8) =
            *(const uint4*)(qg + (size_t)head * NN * DH_ + row * 64 + cg * 8);
    }

    unsigned sb;
    asm("{ .reg .u64 t; cvta.to.shared.u64 t, %1; cvt.u32.u64 %0, t; }"
        : "=r"(sb) : "l"(sh));
    const unsigned ldQ = sb + (unsigned)(hw * 4608 + (wr + (lane & 15)) * TSTR
                                         + ((lane >> 4) << 3)) * 2u;
    const unsigned ldK = sb + (unsigned)(9216 + ((lane & 7) + ((lane >> 4) << 3)) * TSTR
                                         + (((lane >> 3) & 1) << 3)) * 2u;
    const unsigned ldV = sb + (unsigned)(13824 + ((lane & 7) + (((lane >> 3) & 1) << 3)) * TSTR
                                         + ((lane >> 4) << 3)) * 2u;

    const __half* kg = g_kh + ((size_t)(b * HH + h)) * NN * DH_;
    const __half* vg = g_vh + ((size_t)(b * HH + h)) * NN * DH_;

    float ofrag[8][4];
    float mrow[2] = {-3.0e38f, -3.0e38f};
    float lrow[2] = {0.f, 0.f};
    #pragma unroll
    for (int nt = 0; nt < 8; nt++) {
        #pragma unroll
        for (int q = 0; q < 4; q++) ofrag[nt][q] = 0.f;
    }

    for (int jt = 0; jt <= qt; jt++) {
        __syncthreads();
        #pragma unroll
        for (int it = 0; it < 2; it++) {
            int u = tid + it * 256;
            int row = u >> 3, cg = u & 7;
            size_t go = (size_t)(jt * 64 + row) * 64 + cg * 8;
            *(uint4*)(sh + 9216 + row * TSTR + cg * 8)  = *(const uint4*)(kg + go);
            *(uint4*)(sh + 13824 + row * TSTR + cg * 8) = *(const uint4*)(vg + go);
        }
        __syncthreads();

        float sfrag[8][4];
        #pragma unroll
        for (int nt = 0; nt < 8; nt++) {
            #pragma unroll
            for (int q = 0; q < 4; q++) sfrag[nt][q] = 0.f;
        }
        #pragma unroll
        for (int ks = 0; ks < 4; ks++) {
            unsigned a[4];
            ldsm4(a[0], a[1], a[2], a[3], ldQ + ks * 32);
            #pragma unroll
            for (int np = 0; np < 4; np++) {
                unsigned bf[4];
                ldsm4(bf[0], bf[1], bf[2], bf[3],
                      ldK + (unsigned)(np * 16 * TSTR * 2) + ks * 32);
                mma16816(sfrag[2 * np],     a, bf[0], bf[1]);
                mma16816(sfrag[2 * np + 1], a, bf[2], bf[3]);
            }
        }

        const bool diag = (jt == qt);
        #pragma unroll
        for (int r2 = 0; r2 < 2; r2++) {
            const int ig = wr + er + 8 * r2;
            float mx = -3.0e38f;
            #pragma unroll
            for (int nt = 0; nt < 8; nt++) {
                #pragma unroll
                for (int c = 0; c < 2; c++) {
                    float s = sfrag[nt][2 * r2 + c];
                    // tanh(s*0.02)*6.25 via exp:  tanh(y) = 1 - 2/(e^{2y}+1)
                    float e = __expf(s * 0.04f);
                    float x = (1.f - __fdividef(2.f, e + 1.f)) * 6.25f;
                    if (diag && (nt * 8 + ec + c > ig)) x = -3.0e38f;
                    sfrag[nt][2 * r2 + c] = x;
                    mx = fmaxf(mx, x);
                }
            }
            mx = fmaxf(mx, __shfl_xor_sync(~0u, mx, 1));
            mx = fmaxf(mx, __shfl_xor_sync(~0u, mx, 2));
            float mn = fmaxf(mrow[r2], mx);
            float alpha = __expf(mrow[r2] - mn);
            mrow[r2] = mn;
            float ps = 0.f;
            #pragma unroll
            for (int nt = 0; nt < 8; nt++) {
                #pragma unroll
                for (int c = 0; c < 2; c++) {
                    float p = __expf(sfrag[nt][2 * r2 + c] - mn);
                    sfrag[nt][2 * r2 + c] = p;
                    ps += p;
                }
            }
            ps += __shfl_xor_sync(~0u, ps, 1);
            ps += __shfl_xor_sync(~0u, ps, 2);
            lrow[r2] = lrow[r2] * alpha + ps;
            #pragma unroll
            for (int nt = 0; nt < 8; nt++) {
                ofrag[nt][2 * r2]     *= alpha;
                ofrag[nt][2 * r2 + 1] *= alpha;
            }
        }

        unsigned pa[8][2];
        #pragma unroll
        for (int nt = 0; nt < 8; nt++) {
            __half2 h0 = __floats2half2_rn(sfrag[nt][0], sfrag[nt][1]);
            __half2 h1 = __floats2half2_rn(sfrag[nt][2], sfrag[nt][3]);
            pa[nt][0] = *(unsigned*)&h0;
            pa[nt][1] = *(unsigned*)&h1;
        }

        #pragma unroll
        for (int kv = 0; kv < 4; kv++) {
            unsigned a[4] = {pa[2 * kv][0], pa[2 * kv][1],
                             pa[2 * kv + 1][0], pa[2 * kv + 1][1]};
            #pragma unroll
            for (int np = 0; np < 4; np++) {
                unsigned bf[4];
                ldsm4t(bf[0], bf[1], bf[2], bf[3],
                       ldV + (unsigned)(kv * 16 * TSTR * 2) + np * 32);
                mma16816(ofrag[2 * np],     a, bf[0], bf[1]);
                mma16816(ofrag[2 * np + 1], a, bf[2], bf[3]);
            }
        }
    }

    const float inv0 = 1.0f / lrow[0];
    const float inv1 = 1.0f / lrow[1];
    __syncthreads();
    if (hw == 1) {
        #pragma unroll
        for (int nt = 0; nt < 8; nt++) {
            Obuf[(wr + er) * 66 + nt * 8 + ec]         = ofrag[nt][0] * inv0;
            Obuf[(wr + er) * 66 + nt * 8 + ec + 1]     = ofrag[nt][1] * inv0;
            Obuf[(wr + er + 8) * 66 + nt * 8 + ec]     = ofrag[nt][2] * inv1;
            Obuf[(wr + er + 8) * 66 + nt * 8 + ec + 1] = ofrag[nt][3] * inv1;
        }
    }
    __syncthreads();
    if (hw == 0) {
        size_t gr0 = (size_t)(b * NN + qt * 64 + wr + er) * (HH * DH_) + h * DH_;
        size_t gr1 = gr0 + 8 * (HH * DH_);
        #pragma unroll
        for (int nt = 0; nt < 8; nt++) {
            float o0 = ofrag[nt][0] * inv0 + Obuf[(wr + er) * 66 + nt * 8 + ec];
            float o1 = ofrag[nt][1] * inv0 + Obuf[(wr + er) * 66 + nt * 8 + ec + 1];
            float o2 = ofrag[nt][2] * inv1 + Obuf[(wr + er + 8) * 66 + nt * 8 + ec];
            float o3 = ofrag[nt][3] * inv1 + Obuf[(wr + er + 8) * 66 + nt * 8 + ec + 1];
            *(__half2*)(g_ah + gr0 + nt * 8 + ec) = __floats2half2_rn(o0, o1);
            *(__half2*)(g_ah + gr1 + nt * 8 + ec) = __floats2half2_rn(o2, o3);
        }
    }
}

// ---------------- launch ------------------------------------------------------
extern "C" void kernel_launch(void* const* d_in, const int* in_sizes, int n_in,
                              void* d_out, int out_size) {
    const float* tokens  = (const float*)d_in[0];
    const float* norm_w  = (const float*)d_in[1];
    const float* Wq      = (const float*)d_in[2];
    const float* Wkv     = (const float*)d_in[3];
    const float* Wout    = (const float*)d_in[4];
    const float* q_gamma = (const float*)d_in[5];
    const float* k_gamma = (const float*)d_in[6];
    float* out = (float*)d_out;

    __half *xh, *w, *wo, *ah;
    cudaGetSymbolAddress((void**)&xh, g_xh);
    cudaGetSymbolAddress((void**)&w,  g_w);
    cudaGetSymbolAddress((void**)&wo, g_wo);
    cudaGetSymbolAddress((void**)&ah, g_ah);

    // weight transposes (fp32 -> fp16 [N][K]); Wq rows 0-1023, Wkv rows 1024-2047
    dim3 tb(32, 8);
    wtrans_kernel<<<dim3(32, 32), tb>>>(Wq,  w,                1024, 1024);
    wtrans_kernel<<<dim3(32, 32), tb>>>(Wkv, w + 1024 * 1024,  1024, 1024);
    wtrans_kernel<<<dim3(32, 16), tb>>>(Wout, wo,              512, 1024);

    // rmsnorm -> fp16
    rmsnorm_kernel<<<MM, 256>>>(tokens, norm_w);

    // fused QKV projection + per-head norms (one launch)
    qkv_gemm_kernel<<<dim3(16, 32), 256>>>(xh, w, q_gamma, k_gamma);

    // tensor-core attention (group-summed, writes g_ah fp16 directly)
    dim3 agrid(NN / 64, HH, BB);
    attn_kernel<<<agrid, 256>>>();

    // output projection
    hgemm_kernel<<<dim3(8, 32), 256>>>(ah, wo, out, 512);
}

// round 6
// speedup vs baseline: 6.4342x; 1.0183x over previous
#include <cuda_runtime.h>
#include <cuda_fp16.h>
#include <cstdint>
#include <math.h>

#define BB 2
#define NN 2048
#define DD 1024
#define HH 8
#define QH_ 16
#define DH_ 64
#define MM (BB*NN)

// ---------------- scratch ----------------------------------------------------
__device__ __half g_xh [MM*DD];            // rmsnorm(x), fp16 [4096][1024]
__device__ __half g_w  [2*DD*DD];          // [Wq^T ; Wkv^T] fp16 [2048][1024]
__device__ __half g_wo [DD*HH*DH_];        // Wout^T fp16 [1024][512]
__device__ __half g_qh [BB*QH_*NN*DH_];    // normalized q fp16 [b][qh][n][dh]
__device__ __half g_kh [BB*HH*NN*DH_];     // normalized k fp16 [b][h][n][dh]
__device__ __half g_vh [BB*HH*NN*DH_];     // v fp16           [b][h][n][dh]
__device__ __half g_ah [MM*HH*DH_];        // group-summed attn out fp16 [4096][512]

// ---------------- mma / ldmatrix / cp.async helpers ---------------------------
__device__ __forceinline__ void ldsm4(unsigned& r0, unsigned& r1, unsigned& r2,
                                      unsigned& r3, unsigned addr) {
    asm volatile("ldmatrix.sync.aligned.m8n8.x4.shared.b16 {%0,%1,%2,%3}, [%4];"
                 : "=r"(r0), "=r"(r1), "=r"(r2), "=r"(r3) : "r"(addr));
}
__device__ __forceinline__ void ldsm4t(unsigned& r0, unsigned& r1, unsigned& r2,
                                       unsigned& r3, unsigned addr) {
    asm volatile("ldmatrix.sync.aligned.m8n8.x4.trans.shared.b16 {%0,%1,%2,%3}, [%4];"
                 : "=r"(r0), "=r"(r1), "=r"(r2), "=r"(r3) : "r"(addr));
}
__device__ __forceinline__ void mma16816(float* c, const unsigned* a,
                                         unsigned b0, unsigned b1) {
    asm volatile(
        "mma.sync.aligned.m16n8k16.row.col.f32.f16.f16.f32 "
        "{%0,%1,%2,%3},{%4,%5,%6,%7},{%8,%9},{%0,%1,%2,%3};"
        : "+f"(c[0]), "+f"(c[1]), "+f"(c[2]), "+f"(c[3])
        : "r"(a[0]), "r"(a[1]), "r"(a[2]), "r"(a[3]), "r"(b0), "r"(b1));
}
__device__ __forceinline__ void cpa16(unsigned dst, const void* src) {
    asm volatile("cp.async.cg.shared.global [%0], [%1], 16;" :: "r"(dst), "l"(src));
}
#define CP_COMMIT() asm volatile("cp.async.commit_group;")
#define CP_WAIT(n)  asm volatile("cp.async.wait_group %0;" :: "n"(n))

// ---------------- rmsnorm -> fp16, one warp per row ---------------------------
__global__ void rmsnorm_kernel(const float* __restrict__ x,
                               const float* __restrict__ w) {
    const int row = blockIdx.x * 8 + (threadIdx.x >> 5);
    const int lane = threadIdx.x & 31;
    const float4* xr = (const float4*)(x + (size_t)row * DD);
    float4 xv[8];
    float ss = 0.f;
    #pragma unroll
    for (int i = 0; i < 8; i++) {
        xv[i] = xr[lane + 32 * i];
        ss += xv[i].x * xv[i].x + xv[i].y * xv[i].y
            + xv[i].z * xv[i].z + xv[i].w * xv[i].w;
    }
    #pragma unroll
    for (int o = 16; o; o >>= 1) ss += __shfl_xor_sync(~0u, ss, o);
    const float r = rsqrtf(ss * (1.0f / DD) + 1.1920929e-07f);
    const float4* wr = (const float4*)w;
    uint2* yr = (uint2*)(g_xh + (size_t)row * DD);
    #pragma unroll
    for (int i = 0; i < 8; i++) {
        float4 wv = wr[lane + 32 * i];
        __half2 h0 = __floats2half2_rn(xv[i].x * r * wv.x, xv[i].y * r * wv.y);
        __half2 h1 = __floats2half2_rn(xv[i].z * r * wv.z, xv[i].w * r * wv.w);
        uint2 u;
        u.x = *(unsigned*)&h0;
        u.y = *(unsigned*)&h1;
        yr[lane + 32 * i] = u;
    }
}

// ---------------- weight transpose+convert -----------------------------------
// z=0: Wq -> g_w rows 0-1023 ; z=1: Wkv -> g_w rows 1024-2047 (both 1024x1024)
__global__ void wtransqkv_kernel(const float* __restrict__ Wq,
                                 const float* __restrict__ Wkv) {
    __shared__ float t[32][33];
    const float* W = blockIdx.z ? Wkv : Wq;
    __half* Wt = g_w + (size_t)blockIdx.z * DD * DD;
    int n0 = blockIdx.x * 32, k0 = blockIdx.y * 32;
    int x = threadIdx.x, y = threadIdx.y;
    #pragma unroll
    for (int i = 0; i < 32; i += 8)
        t[y + i][x] = W[(size_t)(k0 + y + i) * DD + n0 + x];
    __syncthreads();
    #pragma unroll
    for (int i = 0; i < 32; i += 8)
        Wt[(size_t)(n0 + y + i) * DD + k0 + x] = __float2half(t[x][y + i]);
}
__global__ void wtrans_kernel(const float* __restrict__ W, __half* __restrict__ Wt,
                              int K, int N) {
    __shared__ float t[32][33];
    int n0 = blockIdx.x * 32, k0 = blockIdx.y * 32;
    int x = threadIdx.x, y = threadIdx.y;
    #pragma unroll
    for (int i = 0; i < 32; i += 8)
        t[y + i][x] = W[(size_t)(k0 + y + i) * N + n0 + x];
    __syncthreads();
    #pragma unroll
    for (int i = 0; i < 32; i += 8)
        Wt[(size_t)(n0 + y + i) * K + k0 + x] = __float2half(t[x][y + i]);
}

#define ASTR 40
#define ABUF (128*ASTR)

// ---------------- fused QKV GEMM + per-head norm epilogue --------------------
__global__ void __launch_bounds__(256, 2)
qkv_gemm_kernel(const __half* __restrict__ A, const __half* __restrict__ Bt,
                const float* __restrict__ q_gamma,
                const float* __restrict__ k_gamma) {
    __shared__ __half sh[4 * ABUF];
    const int K = 1024;
    const int tid = threadIdx.x;
    const int lane = tid & 31;
    const int warp = tid >> 5;
    const int wm = (warp >> 1) << 5;
    const int wn = (warp & 1) << 6;
    const int bm = blockIdx.y << 7;
    const int bn = blockIdx.x << 7;

    const int lr = tid >> 2;
    const int lg = (tid & 3) << 3;
    const __half* Ag = A + (size_t)(bm + lr) * K + lg;
    const __half* Bg = Bt + (size_t)(bn + lr) * K + lg;
    const size_t rowskip = (size_t)64 * K;

    unsigned sb;
    asm("{ .reg .u64 t; cvta.to.shared.u64 t, %1; cvt.u32.u64 %0, t; }"
        : "=r"(sb) : "l"(sh));
    const int aRow = wm + (lane & 15);
    const int aK   = (lane >> 4) << 3;
    const int bRow = wn + (lane & 7) + ((lane >> 4) << 3);
    const int bK   = ((lane >> 3) & 1) << 3;
    const unsigned ldA = sb + (unsigned)(aRow * ASTR + aK) * 2u;
    const unsigned ldB = sb + (unsigned)(2 * ABUF + bRow * ASTR + bK) * 2u;

    float acc[2][8][4];
    #pragma unroll
    for (int i = 0; i < 2; i++) {
        #pragma unroll
        for (int j = 0; j < 8; j++) {
            #pragma unroll
            for (int q = 0; q < 4; q++) acc[i][j][q] = 0.f;
        }
    }

    uint4 pa0 = *(const uint4*)Ag;
    uint4 pa1 = *(const uint4*)(Ag + rowskip);
    uint4 pb0 = *(const uint4*)Bg;
    uint4 pb1 = *(const uint4*)(Bg + rowskip);
    {
        __half* as = sh + lr * ASTR + lg;
        __half* bs = sh + 2 * ABUF + lr * ASTR + lg;
        *(uint4*)as = pa0;
        *(uint4*)(as + 64 * ASTR) = pa1;
        *(uint4*)bs = pb0;
        *(uint4*)(bs + 64 * ASTR) = pb1;
    }
    __syncthreads();

    const int nch = K >> 5;
    for (int c = 0; c < nch; c++) {
        if (c + 1 < nch) {
            const __half* An = Ag + (c + 1) * 32;
            const __half* Bn = Bg + (c + 1) * 32;
            pa0 = *(const uint4*)An;
            pa1 = *(const uint4*)(An + rowskip);
            pb0 = *(const uint4*)Bn;
            pb1 = *(const uint4*)(Bn + rowskip);
        }
        const unsigned bo = (unsigned)(c & 1) * (unsigned)(ABUF * 2);
        #pragma unroll
        for (int ks = 0; ks < 2; ks++) {
            unsigned a0r[4], a1r[4], b[4][4];
            ldsm4(a0r[0], a0r[1], a0r[2], a0r[3], ldA + bo + ks * 32);
            ldsm4(a1r[0], a1r[1], a1r[2], a1r[3],
                  ldA + bo + 16 * ASTR * 2 + ks * 32);
            #pragma unroll
            for (int p = 0; p < 4; p++)
                ldsm4(b[p][0], b[p][1], b[p][2], b[p][3],
                      ldB + bo + (unsigned)(p * 16 * ASTR * 2) + ks * 32);
            #pragma unroll
            for (int p = 0; p < 4; p++) {
                mma16816(acc[0][2 * p],     a0r, b[p][0], b[p][1]);
                mma16816(acc[0][2 * p + 1], a0r, b[p][2], b[p][3]);
                mma16816(acc[1][2 * p],     a1r, b[p][0], b[p][1]);
                mma16816(acc[1][2 * p + 1], a1r, b[p][2], b[p][3]);
            }
        }
        if (c + 1 < nch) {
            __syncthreads();
            __half* as = sh + ((c + 1) & 1) * ABUF + lr * ASTR + lg;
            __half* bs = as + 2 * ABUF;
            *(uint4*)as = pa0;
            *(uint4*)(as + 64 * ASTR) = pa1;
            *(uint4*)bs = pb0;
            *(uint4*)(bs + 64 * ASTR) = pb1;
            __syncthreads();
        }
    }

    // ---- fused epilogue: per-head l2norm / convert ----
    const int er = lane >> 2;
    const int ec = (lane & 3) << 1;
    const int colbase = bn + wn;
    int head, nh;
    __half* darr;
    const float* gp;
    if (colbase < 1024)      { head = colbase >> 6;          darr = g_qh; gp = q_gamma + head * 64; nh = 16; }
    else if (colbase < 1536) { head = (colbase - 1024) >> 6; darr = g_kh; gp = k_gamma + head * 64; nh = 8; }
    else                     { head = (colbase - 1536) >> 6; darr = g_vh; gp = nullptr;             nh = 8; }

    float gs[8][2];
    #pragma unroll
    for (int nt = 0; nt < 8; nt++) {
        if (gp) {
            gs[nt][0] = (gp[nt * 8 + ec] + 1.f) * 8.f;
            gs[nt][1] = (gp[nt * 8 + ec + 1] + 1.f) * 8.f;
        } else {
            gs[nt][0] = 1.f;
            gs[nt][1] = 1.f;
        }
    }

    #pragma unroll
    for (int mt = 0; mt < 2; mt++) {
        #pragma unroll
        for (int rh = 0; rh < 2; rh++) {
            float s = 0.f;
            #pragma unroll
            for (int nt = 0; nt < 8; nt++) {
                float v0 = acc[mt][nt][2 * rh];
                float v1 = acc[mt][nt][2 * rh + 1];
                s = fmaf(v0, v0, fmaf(v1, v1, s));
            }
            s += __shfl_xor_sync(~0u, s, 1);
            s += __shfl_xor_sync(~0u, s, 2);
            float iv = gp ? (1.0f / fmaxf(sqrtf(s), 1e-12f)) : 1.0f;

            int m = bm + wm + mt * 16 + rh * 8 + er;
            int b = m >> 11, n = m & (NN - 1);
            __half* drow = darr + (((size_t)(b * nh + head)) * NN + n) * DH_;
            #pragma unroll
            for (int nt = 0; nt < 8; nt++) {
                float o0 = acc[mt][nt][2 * rh] * iv * gs[nt][0];
                float o1 = acc[mt][nt][2 * rh + 1] * iv * gs[nt][1];
                *(__half2*)(drow + nt * 8 + ec) = __floats2half2_rn(o0, o1);
            }
        }
    }
}

// ---------------- out-proj GEMM ------------------------------------------------
__global__ void __launch_bounds__(256, 2)
hgemm_kernel(const __half* __restrict__ A, const __half* __restrict__ Bt,
             float* __restrict__ C, int K) {
    __shared__ __half sh[4 * ABUF];
    const int tid = threadIdx.x;
    const int lane = tid & 31;
    const int warp = tid >> 5;
    const int wm = (warp >> 1) << 5;
    const int wn = (warp & 1) << 6;
    const int bm = blockIdx.y << 7;
    const int bn = blockIdx.x << 7;

    const int lr = tid >> 2;
    const int lg = (tid & 3) << 3;
    const __half* Ag = A + (size_t)(bm + lr) * K + lg;
    const __half* Bg = Bt + (size_t)(bn + lr) * K + lg;
    const size_t rowskip = (size_t)64 * K;

    unsigned sb;
    asm("{ .reg .u64 t; cvta.to.shared.u64 t, %1; cvt.u32.u64 %0, t; }"
        : "=r"(sb) : "l"(sh));
    const int aRow = wm + (lane & 15);
    const int aK   = (lane >> 4) << 3;
    const int bRow = wn + (lane & 7) + ((lane >> 4) << 3);
    const int bK   = ((lane >> 3) & 1) << 3;
    const unsigned ldA = sb + (unsigned)(aRow * ASTR + aK) * 2u;
    const unsigned ldB = sb + (unsigned)(2 * ABUF + bRow * ASTR + bK) * 2u;

    float acc[2][8][4];
    #pragma unroll
    for (int i = 0; i < 2; i++) {
        #pragma unroll
        for (int j = 0; j < 8; j++) {
            #pragma unroll
            for (int q = 0; q < 4; q++) acc[i][j][q] = 0.f;
        }
    }

    uint4 pa0 = *(const uint4*)Ag;
    uint4 pa1 = *(const uint4*)(Ag + rowskip);
    uint4 pb0 = *(const uint4*)Bg;
    uint4 pb1 = *(const uint4*)(Bg + rowskip);
    {
        __half* as = sh + lr * ASTR + lg;
        __half* bs = sh + 2 * ABUF + lr * ASTR + lg;
        *(uint4*)as = pa0;
        *(uint4*)(as + 64 * ASTR) = pa1;
        *(uint4*)bs = pb0;
        *(uint4*)(bs + 64 * ASTR) = pb1;
    }
    __syncthreads();

    const int nch = K >> 5;
    for (int c = 0; c < nch; c++) {
        if (c + 1 < nch) {
            const __half* An = Ag + (c + 1) * 32;
            const __half* Bn = Bg + (c + 1) * 32;
            pa0 = *(const uint4*)An;
            pa1 = *(const uint4*)(An + rowskip);
            pb0 = *(const uint4*)Bn;
            pb1 = *(const uint4*)(Bn + rowskip);
        }
        const unsigned bo = (unsigned)(c & 1) * (unsigned)(ABUF * 2);
        #pragma unroll
        for (int ks = 0; ks < 2; ks++) {
            unsigned a0r[4], a1r[4], b[4][4];
            ldsm4(a0r[0], a0r[1], a0r[2], a0r[3], ldA + bo + ks * 32);
            ldsm4(a1r[0], a1r[1], a1r[2], a1r[3],
                  ldA + bo + 16 * ASTR * 2 + ks * 32);
            #pragma unroll
            for (int p = 0; p < 4; p++)
                ldsm4(b[p][0], b[p][1], b[p][2], b[p][3],
                      ldB + bo + (unsigned)(p * 16 * ASTR * 2) + ks * 32);
            #pragma unroll
            for (int p = 0; p < 4; p++) {
                mma16816(acc[0][2 * p],     a0r, b[p][0], b[p][1]);
                mma16816(acc[0][2 * p + 1], a0r, b[p][2], b[p][3]);
                mma16816(acc[1][2 * p],     a1r, b[p][0], b[p][1]);
                mma16816(acc[1][2 * p + 1], a1r, b[p][2], b[p][3]);
            }
        }
        if (c + 1 < nch) {
            __syncthreads();
            __half* as = sh + ((c + 1) & 1) * ABUF + lr * ASTR + lg;
            __half* bs = as + 2 * ABUF;
            *(uint4*)as = pa0;
            *(uint4*)(as + 64 * ASTR) = pa1;
            *(uint4*)bs = pb0;
            *(uint4*)(bs + 64 * ASTR) = pb1;
            __syncthreads();
        }
    }

    const int er = lane >> 2;
    const int ec = (lane & 3) << 1;
    #pragma unroll
    for (int mt = 0; mt < 2; mt++) {
        #pragma unroll
        for (int nt = 0; nt < 8; nt++) {
            int r0 = bm + wm + mt * 16 + er;
            int c0 = bn + wn + nt * 8 + ec;
            *(float2*)&C[(size_t)r0 * 1024 + c0] =
                make_float2(acc[mt][nt][0], acc[mt][nt][1]);
            *(float2*)&C[(size_t)(r0 + 8) * 1024 + c0] =
                make_float2(acc[mt][nt][2], acc[mt][nt][3]);
        }
    }
}

// ---------------- tensor-core flash attention, cp.async double-buffered ------
// smem halves: Q[2][64][72] @0, K[2][64][72] @9216, V[2][64][72] @18432 (54 KB)
#define TSTR 72
#define QOFF 0
#define KOFF 9216
#define VOFF 18432
#define ATT_SMEM (27648 * 2)

__global__ void __launch_bounds__(256) attn_kernel() {
    extern __shared__ __half sh[];
    float* Obuf = (float*)(sh + KOFF);
    const int qt = 31 - blockIdx.x;          // heavy tiles first
    const int h = blockIdx.y, b = blockIdx.z;
    const int tid = threadIdx.x, lane = tid & 31, warp = tid >> 5;
    const int hw = warp >> 2;
    const int wr = (warp & 3) << 4;
    const int er = lane >> 2, ec = (lane & 3) << 1;

    unsigned sb;
    asm("{ .reg .u64 t; cvta.to.shared.u64 t, %1; cvt.u32.u64 %0, t; }"
        : "=r"(sb) : "l"(sh));

    const __half* qg = g_qh + (((size_t)(b * QH_ + 2 * h)) * NN + qt * 64) * DH_;
    const __half* kg = g_kh + ((size_t)(b * HH + h)) * NN * DH_;
    const __half* vg = g_vh + ((size_t)(b * HH + h)) * NN * DH_;

    // prologue: async-load Q (both heads) and K/V tile 0 into buffer 0
    #pragma unroll
    for (int it = 0; it < 4; it++) {
        int u = tid + it * 256;
        int head = u >> 9, row = (u >> 3) & 63, cg = u & 7;
        cpa16(sb + (unsigned)(QOFF + head * 4608 + row * TSTR + cg * 8) * 2u,
              qg + (size_t)head * NN * DH_ + row * 64 + cg * 8);
    }
    {
        int row = tid >> 3, cg = tid & 7;
        #pragma unroll
        for (int it = 0; it < 2; it++) {
            int rr = row + it * 32;
            size_t go = (size_t)rr * 64 + cg * 8;
            cpa16(sb + (unsigned)(KOFF + rr * TSTR + cg * 8) * 2u, kg + go);
            cpa16(sb + (unsigned)(VOFF + rr * TSTR + cg * 8) * 2u, vg + go);
        }
    }
    CP_COMMIT();

    const unsigned ldQ = sb + (unsigned)(QOFF + hw * 4608 + (wr + (lane & 15)) * TSTR
                                         + ((lane >> 4) << 3)) * 2u;
    const unsigned ldK = sb + (unsigned)(KOFF + ((lane & 7) + ((lane >> 4) << 3)) * TSTR
                                         + (((lane >> 3) & 1) << 3)) * 2u;
    const unsigned ldV = sb + (unsigned)(VOFF + ((lane & 7) + (((lane >> 3) & 1) << 3)) * TSTR
                                         + ((lane >> 4) << 3)) * 2u;

    float ofrag[8][4];
    float mrow[2] = {-3.0e38f, -3.0e38f};
    float lrow[2] = {0.f, 0.f};
    #pragma unroll
    for (int nt = 0; nt < 8; nt++) {
        #pragma unroll
        for (int q = 0; q < 4; q++) ofrag[nt][q] = 0.f;
    }

    for (int jt = 0; jt <= qt; jt++) {
        const unsigned bufb = (unsigned)(jt & 1) * 9216u;   // buffer byte offset
        if (jt < qt) {
            // issue next tile into the other buffer
            const unsigned nb = (unsigned)((jt + 1) & 1) * 4608u;  // half offset
            int row = tid >> 3, cg = tid & 7;
            #pragma unroll
            for (int it = 0; it < 2; it++) {
                int rr = row + it * 32;
                size_t go = (size_t)((jt + 1) * 64 + rr) * 64 + cg * 8;
                cpa16(sb + (KOFF + nb + rr * TSTR + cg * 8) * 2u, kg + go);
                cpa16(sb + (VOFF + nb + rr * TSTR + cg * 8) * 2u, vg + go);
            }
            CP_COMMIT();
            CP_WAIT(1);
        } else {
            CP_WAIT(0);
        }
        __syncthreads();

        // ---- S = Q @ K^T ----
        float sfrag[8][4];
        #pragma unroll
        for (int nt = 0; nt < 8; nt++) {
            #pragma unroll
            for (int q = 0; q < 4; q++) sfrag[nt][q] = 0.f;
        }
        #pragma unroll
        for (int ks = 0; ks < 4; ks++) {
            unsigned a[4];
            ldsm4(a[0], a[1], a[2], a[3], ldQ + ks * 32);
            #pragma unroll
            for (int np = 0; np < 4; np++) {
                unsigned bf[4];
                ldsm4(bf[0], bf[1], bf[2], bf[3],
                      ldK + bufb + (unsigned)(np * 16 * TSTR * 2) + ks * 32);
                mma16816(sfrag[2 * np],     a, bf[0], bf[1]);
                mma16816(sfrag[2 * np + 1], a, bf[2], bf[3]);
            }
        }

        // ---- softcap + mask + online softmax ----
        const bool diag = (jt == qt);
        #pragma unroll
        for (int r2 = 0; r2 < 2; r2++) {
            const int ig = wr + er + 8 * r2;
            float mx = -3.0e38f;
            #pragma unroll
            for (int nt = 0; nt < 8; nt++) {
                #pragma unroll
                for (int c = 0; c < 2; c++) {
                    float s = sfrag[nt][2 * r2 + c];
                    float e = __expf(s * 0.04f);
                    float x = (1.f - __fdividef(2.f, e + 1.f)) * 6.25f;
                    if (diag && (nt * 8 + ec + c > ig)) x = -3.0e38f;
                    sfrag[nt][2 * r2 + c] = x;
                    mx = fmaxf(mx, x);
                }
            }
            mx = fmaxf(mx, __shfl_xor_sync(~0u, mx, 1));
            mx = fmaxf(mx, __shfl_xor_sync(~0u, mx, 2));
            float mn = fmaxf(mrow[r2], mx);
            float alpha = __expf(mrow[r2] - mn);
            mrow[r2] = mn;
            float ps = 0.f;
            #pragma unroll
            for (int nt = 0; nt < 8; nt++) {
                #pragma unroll
                for (int c = 0; c < 2; c++) {
                    float p = __expf(sfrag[nt][2 * r2 + c] - mn);
                    sfrag[nt][2 * r2 + c] = p;
                    ps += p;
                }
            }
            ps += __shfl_xor_sync(~0u, ps, 1);
            ps += __shfl_xor_sync(~0u, ps, 2);
            lrow[r2] = lrow[r2] * alpha + ps;
            #pragma unroll
            for (int nt = 0; nt < 8; nt++) {
                ofrag[nt][2 * r2]     *= alpha;
                ofrag[nt][2 * r2 + 1] *= alpha;
            }
        }

        unsigned pa[8][2];
        #pragma unroll
        for (int nt = 0; nt < 8; nt++) {
            __half2 h0 = __floats2half2_rn(sfrag[nt][0], sfrag[nt][1]);
            __half2 h1 = __floats2half2_rn(sfrag[nt][2], sfrag[nt][3]);
            pa[nt][0] = *(unsigned*)&h0;
            pa[nt][1] = *(unsigned*)&h1;
        }

        // ---- O += P @ V ----
        #pragma unroll
        for (int kv = 0; kv < 4; kv++) {
            unsigned a[4] = {pa[2 * kv][0], pa[2 * kv][1],
                             pa[2 * kv + 1][0], pa[2 * kv + 1][1]};
            #pragma unroll
            for (int np = 0; np < 4; np++) {
                unsigned bf[4];
                ldsm4t(bf[0], bf[1], bf[2], bf[3],
                       ldV + bufb + (unsigned)(kv * 16 * TSTR * 2) + np * 32);
                mma16816(ofrag[2 * np],     a, bf[0], bf[1]);
                mma16816(ofrag[2 * np + 1], a, bf[2], bf[3]);
            }
        }
        __syncthreads();    // all reads of this buffer done before it is refilled
    }

    // ---- combine group heads + write fp16 ----
    const float inv0 = 1.0f / lrow[0];
    const float inv1 = 1.0f / lrow[1];
    if (hw == 1) {
        #pragma unroll
        for (int nt = 0; nt < 8; nt++) {
            Obuf[(wr + er) * 66 + nt * 8 + ec]         = ofrag[nt][0] * inv0;
            Obuf[(wr + er) * 66 + nt * 8 + ec + 1]     = ofrag[nt][1] * inv0;
            Obuf[(wr + er + 8) * 66 + nt * 8 + ec]     = ofrag[nt][2] * inv1;
            Obuf[(wr + er + 8) * 66 + nt * 8 + ec + 1] = ofrag[nt][3] * inv1;
        }
    }
    __syncthreads();
    if (hw == 0) {
        size_t gr0 = (size_t)(b * NN + qt * 64 + wr + er) * (HH * DH_) + h * DH_;
        size_t gr1 = gr0 + 8 * (HH * DH_);
        #pragma unroll
        for (int nt = 0; nt < 8; nt++) {
            float o0 = ofrag[nt][0] * inv0 + Obuf[(wr + er) * 66 + nt * 8 + ec];
            float o1 = ofrag[nt][1] * inv0 + Obuf[(wr + er) * 66 + nt * 8 + ec + 1];
            float o2 = ofrag[nt][2] * inv1 + Obuf[(wr + er + 8) * 66 + nt * 8 + ec];
            float o3 = ofrag[nt][3] * inv1 + Obuf[(wr + er + 8) * 66 + nt * 8 + ec + 1];
            *(__half2*)(g_ah + gr0 + nt * 8 + ec) = __floats2half2_rn(o0, o1);
            *(__half2*)(g_ah + gr1 + nt * 8 + ec) = __floats2half2_rn(o2, o3);
        }
    }
}

// ---------------- launch ------------------------------------------------------
extern "C" void kernel_launch(void* const* d_in, const int* in_sizes, int n_in,
                              void* d_out, int out_size) {
    const float* tokens  = (const float*)d_in[0];
    const float* norm_w  = (const float*)d_in[1];
    const float* Wq      = (const float*)d_in[2];
    const float* Wkv     = (const float*)d_in[3];
    const float* Wout    = (const float*)d_in[4];
    const float* q_gamma = (const float*)d_in[5];
    const float* k_gamma = (const float*)d_in[6];
    float* out = (float*)d_out;

    __half *xh, *w, *wo, *ah;
    cudaGetSymbolAddress((void**)&xh, g_xh);
    cudaGetSymbolAddress((void**)&w,  g_w);
    cudaGetSymbolAddress((void**)&wo, g_wo);
    cudaGetSymbolAddress((void**)&ah, g_ah);

    // weight transposes
    dim3 tb(32, 8);
    wtransqkv_kernel<<<dim3(32, 32, 2), tb>>>(Wq, Wkv);
    wtrans_kernel<<<dim3(32, 16), tb>>>(Wout, wo, 512, 1024);

    // rmsnorm -> fp16 (warp per row)
    rmsnorm_kernel<<<MM / 8, 256>>>(tokens, norm_w);

    // fused QKV projection + per-head norms
    qkv_gemm_kernel<<<dim3(16, 32), 256>>>(xh, w, q_gamma, k_gamma);

    // tensor-core attention, cp.async double-buffered
    cudaFuncSetAttribute(attn_kernel, cudaFuncAttributeMaxDynamicSharedMemorySize,
                         ATT_SMEM);
    dim3 agrid(NN / 64, HH, BB);
    attn_kernel<<<agrid, 256, ATT_SMEM>>>();

    // output projection
    hgemm_kernel<<<dim3(8, 32), 256>>>(ah, wo, out, 512);
}